// round 12
// baseline (speedup 1.0000x reference)
#include <cuda_runtime.h>
#include <cuda_bf16.h>

// B=4, N=4096, D=64, H=256.
// out[b,q,dv] = (softmax_k( -0.5*cdistL1(Ks,Qs)^2 ) @ V) * Wo
//   Ks = KEY*mlp(KEY), Qs = QUERY*mlp(QUERY), Wo = mlpo(QUERY)
// L1 dist(k,q) = sk[k] + sq[q] - 2*sum_d min(Ks,Qs); flash softmax tracks min score.

#define NB   4
#define NSEQ 4096
#define DD   64
#define NROWS (NB * NSEQ)

__device__ float g_Ks[NROWS * DD];
__device__ float g_Qs[NROWS * DD];
__device__ float g_Wo[NROWS * DD];
__device__ float g_sk[NROWS];
__device__ float g_sq[NROWS];

// ---- packed fp32x2 (Blackwell FADD2/FFMA2, only reachable via PTX) ----
__device__ __forceinline__ void addx2(float& ax, float& ay, float bx, float by) {
    asm("{\n\t.reg .b64 ra, rb;\n\t"
        "mov.b64 ra, {%0, %1};\n\t"
        "mov.b64 rb, {%2, %3};\n\t"
        "add.rn.f32x2 ra, ra, rb;\n\t"
        "mov.b64 {%0, %1}, ra;\n\t}"
        : "+f"(ax), "+f"(ay) : "f"(bx), "f"(by));
}
__device__ __forceinline__ void fmax2(float& cx, float& cy, float ax, float ay,
                                      float bx, float by) {
    asm("{\n\t.reg .b64 rc, ra, rb;\n\t"
        "mov.b64 rc, {%0, %1};\n\t"
        "mov.b64 ra, {%2, %3};\n\t"
        "mov.b64 rb, {%4, %5};\n\t"
        "fma.rn.f32x2 rc, ra, rb, rc;\n\t"
        "mov.b64 {%0, %1}, rc;\n\t}"
        : "+f"(cx), "+f"(cy) : "f"(ax), "f"(ay), "f"(bx), "f"(by));
}
__device__ __forceinline__ float dupreg(float x) {
    float y;
    asm volatile("mov.f32 %0, %1;" : "=f"(y) : "f"(x));
    return y;
}

// ---------------------------------------------------------------------------
// MLP kernel. One block = 64 rows, 256 threads, occ 1 (217KB smem).
// Per-thread tile 8 rows x 8 outs -> 32 FFMA2 per i-step.
// mode: 0 KEY->Ks,sk ; 1 QUERY->Qs,sq ; 2 QUERY->Wo.
// ---------------------------------------------------------------------------
#define MLP_SMEM_FLOATS (64*68 + 64*260 + 64*260 + 64*260)

__global__ void __launch_bounds__(256, 1) mlp_kernel(
    const float* __restrict__ KEY, const float* __restrict__ QUERY,
    const float* __restrict__ W1,  const float* __restrict__ B1,
    const float* __restrict__ W2,  const float* __restrict__ B2,
    const float* __restrict__ W3,  const float* __restrict__ B3,
    const float* __restrict__ W1o, const float* __restrict__ B1o,
    const float* __restrict__ W2o, const float* __restrict__ B2o,
    const float* __restrict__ W3o, const float* __restrict__ B3o)
{
    extern __shared__ float sm[];
    float* s_x = sm;              // 64*68
    float* s_a = s_x + 64 * 68;   // 64*260
    float* s_b = s_a + 64 * 260;  // 64*260
    float* s_w = s_b + 64 * 260;  // 64*260 (transposed weight chunk [in][out])

    const int t    = threadIdx.x;
    const int mode = blockIdx.y;
    const int row0 = blockIdx.x * 64;

    const float* X  = (mode == 0) ? KEY : QUERY;
    const float* w1 = (mode < 2) ? W1 : W1o;
    const float* b1 = (mode < 2) ? B1 : B1o;
    const float* w2 = (mode < 2) ? W2 : W2o;
    const float* b2 = (mode < 2) ? B2 : B2o;
    const float* w3 = (mode < 2) ? W3 : W3o;
    const float* b3 = (mode < 2) ? B3 : B3o;

    // input tile 64x64
    for (int idx = t; idx < 64 * 16; idx += 256) {
        int r = idx >> 4, c = (idx & 15) * 4;
        *(float4*)(s_x + r * 68 + c) =
            *(const float4*)(X + (size_t)(row0 + r) * 64 + c);
    }
    // stage W1 (256x64) transposed
    for (int idx = t; idx < 256 * 64; idx += 256) {
        int o = idx >> 6, i = idx & 63;
        s_w[i * 260 + o] = w1[idx];
    }
    __syncthreads();

    const int og = t & 31;   // 32 out-groups of 8 outs
    const int rg = t >> 5;   // 8 row-groups of 8 rows

    // ================= Layer 1: 64 -> 256, relu -> s_a =================
    {
        float acc[8][8];
#pragma unroll
        for (int r = 0; r < 8; r++)
#pragma unroll
            for (int c = 0; c < 8; c++) acc[r][c] = 0.f;

#pragma unroll 2
        for (int i = 0; i < 64; i++) {
            float4 wA = *(const float4*)(s_w + i * 260 + og * 8);
            float4 wB = *(const float4*)(s_w + i * 260 + og * 8 + 4);
#pragma unroll
            for (int r = 0; r < 8; r++) {
                float a  = s_x[(rg * 8 + r) * 68 + i];
                float ad = dupreg(a);
                fmax2(acc[r][0], acc[r][1], a, ad, wA.x, wA.y);
                fmax2(acc[r][2], acc[r][3], a, ad, wA.z, wA.w);
                fmax2(acc[r][4], acc[r][5], a, ad, wB.x, wB.y);
                fmax2(acc[r][6], acc[r][7], a, ad, wB.z, wB.w);
            }
        }
#pragma unroll
        for (int c = 0; c < 8; c++) {
            int o = og * 8 + c;
            float bv = __ldg(b1 + o);
#pragma unroll
            for (int r = 0; r < 8; r++)
                s_a[(rg * 8 + r) * 260 + o] = fmaxf(acc[r][c] + bv, 0.f);
        }
    }

    // ================= Layer 2: 256 -> 256, relu -> s_b =================
    {
        float acc[8][8];
#pragma unroll
        for (int r = 0; r < 8; r++)
#pragma unroll
            for (int c = 0; c < 8; c++) acc[r][c] = 0.f;

        for (int ch = 0; ch < 4; ch++) {
            __syncthreads();
            for (int idx = t; idx < 256 * 64; idx += 256) {
                int o = idx >> 6, i = idx & 63;
                s_w[i * 260 + o] = w2[o * 256 + ch * 64 + i];
            }
            __syncthreads();
#pragma unroll 2
            for (int i = 0; i < 64; i++) {
                float4 wA = *(const float4*)(s_w + i * 260 + og * 8);
                float4 wB = *(const float4*)(s_w + i * 260 + og * 8 + 4);
#pragma unroll
                for (int r = 0; r < 8; r++) {
                    float a  = s_a[(rg * 8 + r) * 260 + ch * 64 + i];
                    float ad = dupreg(a);
                    fmax2(acc[r][0], acc[r][1], a, ad, wA.x, wA.y);
                    fmax2(acc[r][2], acc[r][3], a, ad, wA.z, wA.w);
                    fmax2(acc[r][4], acc[r][5], a, ad, wB.x, wB.y);
                    fmax2(acc[r][6], acc[r][7], a, ad, wB.z, wB.w);
                }
            }
        }
#pragma unroll
        for (int c = 0; c < 8; c++) {
            int o = og * 8 + c;
            float bv = __ldg(b2 + o);
#pragma unroll
            for (int r = 0; r < 8; r++)
                s_b[(rg * 8 + r) * 260 + o] = fmaxf(acc[r][c] + bv, 0.f);
        }
    }

    // ================= Layer 3: 256 -> 64 + epilogue =================
    {
        const int rp = t >> 3;    // 32 row-pairs (2 rows each)
        const int o8 = t & 7;     // 8 out-groups of 8 outs
        float acc3[2][8];
#pragma unroll
        for (int r = 0; r < 2; r++)
#pragma unroll
            for (int c = 0; c < 8; c++) acc3[r][c] = 0.f;

        for (int ch = 0; ch < 4; ch++) {
            __syncthreads();
            for (int idx = t; idx < 64 * 64; idx += 256) {
                int o = idx >> 6, i = idx & 63;
                s_w[i * 260 + o] = w3[o * 256 + ch * 64 + i];
            }
            __syncthreads();
#pragma unroll 4
            for (int i = 0; i < 64; i++) {
                float4 wA = *(const float4*)(s_w + i * 260 + o8 * 8);
                float4 wB = *(const float4*)(s_w + i * 260 + o8 * 8 + 4);
#pragma unroll
                for (int r = 0; r < 2; r++) {
                    float a  = s_b[(rp * 2 + r) * 260 + ch * 64 + i];
                    float ad = dupreg(a);
                    fmax2(acc3[r][0], acc3[r][1], a, ad, wA.x, wA.y);
                    fmax2(acc3[r][2], acc3[r][3], a, ad, wA.z, wA.w);
                    fmax2(acc3[r][4], acc3[r][5], a, ad, wB.x, wB.y);
                    fmax2(acc3[r][6], acc3[r][7], a, ad, wB.z, wB.w);
                }
            }
        }

        float* dst = (mode == 0) ? g_Ks : (mode == 1) ? g_Qs : g_Wo;
#pragma unroll
        for (int r = 0; r < 2; r++) {
            const int row = rp * 2 + r;
            float val[8];
            float sum = 0.f;
#pragma unroll
            for (int c = 0; c < 8; c++) {
                int o = o8 * 8 + c;
                float y = acc3[r][c] + __ldg(b3 + o);
                if (mode < 2) { val[c] = y * s_x[row * 68 + o]; sum += val[c]; }
                else          { val[c] = y; }
            }
            size_t grow = (size_t)(row0 + row);
            *(float4*)(dst + grow * 64 + o8 * 8)     = make_float4(val[0], val[1], val[2], val[3]);
            *(float4*)(dst + grow * 64 + o8 * 8 + 4) = make_float4(val[4], val[5], val[6], val[7]);
            if (mode < 2) {
                sum += __shfl_xor_sync(0xffffffffu, sum, 1);
                sum += __shfl_xor_sync(0xffffffffu, sum, 2);
                sum += __shfl_xor_sync(0xffffffffu, sum, 4);
                if (o8 == 0) ((mode == 0) ? g_sk : g_sq)[grow] = sum;
            }
        }
    }
}

// ---------------------------------------------------------------------------
// Attention. Block = 32 queries (8 warps x 4 q), key chunks of 64, 512 blocks
// (grid was the occupancy cap at 64q). Lane owns 2 keys for scores, dv pair
// {2*lane,2*lane+1} for AV. occ target 4 blocks/SM (53KB smem each).
// ---------------------------------------------------------------------------
#define ATT_SMEM_FLOATS (32*68 + 64*68 + 64*68 + 64*36 + 64 + 32)

__global__ void __launch_bounds__(256, 4) attn_kernel(
    const float* __restrict__ V, float* __restrict__ out)
{
    extern __shared__ float sm[];
    float* s_q  = sm;               // [32][68]  Qs tile
    float* s_k  = s_q + 32 * 68;    // [64][68]  Ks chunk
    float* s_v  = s_k + 64 * 68;    // [64][68]  V chunk
    float* s_p  = s_v + 64 * 68;    // [64][36]  probabilities (col = w*4+j)
    float* s_sk = s_p + 64 * 36;    // [64]
    float* s_sq = s_sk + 64;        // [32]

    const int t    = threadIdx.x;
    const int lane = t & 31;
    const int w    = t >> 5;
    const int w4   = w * 4;
    const int b    = blockIdx.y;
    const int q0   = blockIdx.x * 32;

    const float* Qs = g_Qs + (size_t)b * NSEQ * 64;
    const float* Ks = g_Ks + (size_t)b * NSEQ * 64;
    const float* Vb = V    + (size_t)b * NSEQ * 64;

    for (int idx = t; idx < 32 * 16; idx += 256) {
        int r = idx >> 4, c = (idx & 15) * 4;
        *(float4*)(s_q + r * 68 + c) = *(const float4*)(Qs + (size_t)(q0 + r) * 64 + c);
    }
    if (t < 32) s_sq[t] = g_sq[b * NSEQ + q0 + t];

    float m[4], l[4], accx[4], accy[4];
#pragma unroll
    for (int j = 0; j < 4; j++) {
        m[j] = 1e30f; l[j] = 0.f; accx[j] = 0.f; accy[j] = 0.f;
    }

    const int k0 = lane, k1 = lane + 32;

    for (int kc = 0; kc < NSEQ / 64; kc++) {
        __syncthreads();   // previous chunk fully consumed
        const int kb = kc * 64;
        for (int idx = t; idx < 64 * 16; idx += 256) {
            int r = idx >> 4, c = (idx & 15) * 4;
            *(float4*)(s_k + r * 68 + c) = *(const float4*)(Ks + (size_t)(kb + r) * 64 + c);
            *(float4*)(s_v + r * 68 + c) = *(const float4*)(Vb + (size_t)(kb + r) * 64 + c);
        }
        if (t < 64) s_sk[t] = g_sk[b * NSEQ + kb + t];
        __syncthreads();

        // ---- scores: sum_d min(Ks,Qs), (2 k) x (4 q) per lane ----
        float t0x[4], t0y[4], t1x[4], t1y[4];
#pragma unroll
        for (int j = 0; j < 4; j++) { t0x[j] = t0y[j] = t1x[j] = t1y[j] = 0.f; }

#pragma unroll 2
        for (int d = 0; d < 64; d += 4) {
            float4 a0 = *(const float4*)(s_k + k0 * 68 + d);
            float4 a1 = *(const float4*)(s_k + k1 * 68 + d);
#pragma unroll
            for (int j = 0; j < 4; j++) {
                float4 qv = *(const float4*)(s_q + (w4 + j) * 68 + d);
                addx2(t0x[j], t0y[j], fminf(a0.x, qv.x), fminf(a0.y, qv.y));
                addx2(t0x[j], t0y[j], fminf(a0.z, qv.z), fminf(a0.w, qv.w));
                addx2(t1x[j], t1y[j], fminf(a1.x, qv.x), fminf(a1.y, qv.y));
                addx2(t1x[j], t1y[j], fminf(a1.z, qv.z), fminf(a1.w, qv.w));
            }
        }

        const float skk0 = s_sk[k0];
        const float skk1 = s_sk[k1];
        float p0[4], p1[4];
#pragma unroll
        for (int j = 0; j < 4; j++) {
            float sqj = s_sq[w4 + j];
            float s0 = skk0 + sqj - 2.f * (t0x[j] + t0y[j]);
            float s1 = skk1 + sqj - 2.f * (t1x[j] + t1y[j]);
            float c  = fminf(s0, s1);
#pragma unroll
            for (int off = 16; off >= 1; off >>= 1)
                c = fminf(c, __shfl_xor_sync(0xffffffffu, c, off));
            float mn = fminf(m[j], c);
            if (mn != m[j]) {                 // warp-uniform branch
                float alpha = __expf(0.5f * (mn - m[j]) * (mn + m[j]));
                m[j] = mn;
                l[j]    *= alpha;
                accx[j] *= alpha;
                accy[j] *= alpha;
            }
            p0[j] = __expf(0.5f * (mn - s0) * (mn + s0));
            p1[j] = __expf(0.5f * (mn - s1) * (mn + s1));
            l[j] += p0[j] + p1[j];            // per-lane partial
        }
        *(float4*)(s_p + k0 * 36 + w4) = make_float4(p0[0], p0[1], p0[2], p0[3]);
        *(float4*)(s_p + k1 * 36 + w4) = make_float4(p1[0], p1[1], p1[2], p1[3]);
        __syncwarp();

        // ---- AV: per k: 1 LDS.128 + 1 LDS.64 + 2 mov + 4 FFMA2 (8 FMAs) ----
#pragma unroll 4
        for (int k = 0; k < 64; k++) {
            float4 pA = *(const float4*)(s_p + k * 36 + w4);
            float2 v  = *(const float2*)(s_v + k * 68 + 2 * lane);
            float vdx = dupreg(v.x), vdy = dupreg(v.y);
            fmax2(accx[0], accx[1], pA.x, pA.y, v.x, vdx);
            fmax2(accx[2], accx[3], pA.z, pA.w, v.x, vdx);
            fmax2(accy[0], accy[1], pA.x, pA.y, v.y, vdy);
            fmax2(accy[2], accy[3], pA.z, pA.w, v.y, vdy);
        }
    }

    // final l reduction across lanes, then epilogue out = (acc/l)*Wo
#pragma unroll
    for (int j = 0; j < 4; j++) {
        float r = l[j];
#pragma unroll
        for (int off = 16; off >= 1; off >>= 1)
            r += __shfl_xor_sync(0xffffffffu, r, off);
        int q = q0 + w4 + j;
        float inv = 1.0f / r;
        size_t off2 = ((size_t)b * NSEQ + q) * 64 + 2 * lane;
        float2 wv = *(const float2*)(g_Wo + off2);
        float2 o;
        o.x = accx[j] * inv * wv.x;
        o.y = accy[j] * inv * wv.y;
        *(float2*)(out + off2) = o;
    }
}

// ---------------------------------------------------------------------------
extern "C" void kernel_launch(void* const* d_in, const int* in_sizes, int n_in,
                              void* d_out, int out_size)
{
    (void)in_sizes; (void)n_in; (void)out_size;
    const float* KEY   = (const float*)d_in[0];
    const float* VALUE = (const float*)d_in[1];
    const float* QUERY = (const float*)d_in[2];
    const float* W1w = (const float*)d_in[3],  *W1b = (const float*)d_in[4];
    const float* W2w = (const float*)d_in[5],  *W2b = (const float*)d_in[6];
    const float* W3w = (const float*)d_in[7],  *W3b = (const float*)d_in[8];
    const float* O1w = (const float*)d_in[9],  *O1b = (const float*)d_in[10];
    const float* O2w = (const float*)d_in[11], *O2b = (const float*)d_in[12];
    const float* O3w = (const float*)d_in[13], *O3b = (const float*)d_in[14];

    cudaFuncSetAttribute(mlp_kernel, cudaFuncAttributeMaxDynamicSharedMemorySize,
                         MLP_SMEM_FLOATS * sizeof(float));
    cudaFuncSetAttribute(attn_kernel, cudaFuncAttributeMaxDynamicSharedMemorySize,
                         ATT_SMEM_FLOATS * sizeof(float));

    dim3 mlp_grid(NROWS / 64, 3);
    mlp_kernel<<<mlp_grid, 256, MLP_SMEM_FLOATS * sizeof(float)>>>(
        KEY, QUERY, W1w, W1b, W2w, W2b, W3w, W3b,
        O1w, O1b, O2w, O2b, O3w, O3b);

    dim3 att_grid(NSEQ / 32, NB);
    attn_kernel<<<att_grid, 256, ATT_SMEM_FLOATS * sizeof(float)>>>(
        VALUE, (float*)d_out);
}

// round 13
// speedup vs baseline: 1.0419x; 1.0419x over previous
#include <cuda_runtime.h>
#include <cuda_bf16.h>

// B=4, N=4096, D=64, H=256.
// out[b,q,dv] = (softmax_k( -0.5*cdistL1(Ks,Qs)^2 ) @ V) * Wo
//   Ks = KEY*mlp(KEY), Qs = QUERY*mlp(QUERY), Wo = mlpo(QUERY)
// L1 dist(k,q) = sk[k] + sq[q] - 2*sum_d min(Ks,Qs); flash softmax tracks min score.
// Split-K: keys partitioned into NSPLIT ranges; partial (m,l,acc) merged exactly.

#define NB   4
#define NSEQ 4096
#define DD   64
#define NROWS (NB * NSEQ)
#define NSPLIT 3

__device__ float g_Ks[NROWS * DD];
__device__ float g_Qs[NROWS * DD];
__device__ float g_Wo[NROWS * DD];
__device__ float g_sk[NROWS];
__device__ float g_sq[NROWS];
// split-K partials
__device__ float g_pm[NSPLIT * NROWS];
__device__ float g_pl[NSPLIT * NROWS];
__device__ float g_pacc[(size_t)NSPLIT * NROWS * DD];

// ---- packed fp32x2 (Blackwell FADD2/FFMA2, only reachable via PTX) ----
__device__ __forceinline__ void addx2(float& ax, float& ay, float bx, float by) {
    asm("{\n\t.reg .b64 ra, rb;\n\t"
        "mov.b64 ra, {%0, %1};\n\t"
        "mov.b64 rb, {%2, %3};\n\t"
        "add.rn.f32x2 ra, ra, rb;\n\t"
        "mov.b64 {%0, %1}, ra;\n\t}"
        : "+f"(ax), "+f"(ay) : "f"(bx), "f"(by));
}
__device__ __forceinline__ void fmax2(float& cx, float& cy, float ax, float ay,
                                      float bx, float by) {
    asm("{\n\t.reg .b64 rc, ra, rb;\n\t"
        "mov.b64 rc, {%0, %1};\n\t"
        "mov.b64 ra, {%2, %3};\n\t"
        "mov.b64 rb, {%4, %5};\n\t"
        "fma.rn.f32x2 rc, ra, rb, rc;\n\t"
        "mov.b64 {%0, %1}, rc;\n\t}"
        : "+f"(cx), "+f"(cy) : "f"(ax), "f"(ay), "f"(bx), "f"(by));
}
__device__ __forceinline__ float dupreg(float x) {
    float y;
    asm volatile("mov.f32 %0, %1;" : "=f"(y) : "f"(x));
    return y;
}

// ---------------------------------------------------------------------------
// MLP kernel (unchanged from best). One block = 64 rows, 256 threads, occ 1.
// ---------------------------------------------------------------------------
#define MLP_SMEM_FLOATS (64*68 + 64*260 + 64*260 + 64*260)

__global__ void __launch_bounds__(256, 1) mlp_kernel(
    const float* __restrict__ KEY, const float* __restrict__ QUERY,
    const float* __restrict__ W1,  const float* __restrict__ B1,
    const float* __restrict__ W2,  const float* __restrict__ B2,
    const float* __restrict__ W3,  const float* __restrict__ B3,
    const float* __restrict__ W1o, const float* __restrict__ B1o,
    const float* __restrict__ W2o, const float* __restrict__ B2o,
    const float* __restrict__ W3o, const float* __restrict__ B3o)
{
    extern __shared__ float sm[];
    float* s_x = sm;              // 64*68
    float* s_a = s_x + 64 * 68;   // 64*260
    float* s_b = s_a + 64 * 260;  // 64*260
    float* s_w = s_b + 64 * 260;  // 64*260 (transposed weight chunk [in][out])

    const int t    = threadIdx.x;
    const int mode = blockIdx.y;
    const int row0 = blockIdx.x * 64;

    const float* X  = (mode == 0) ? KEY : QUERY;
    const float* w1 = (mode < 2) ? W1 : W1o;
    const float* b1 = (mode < 2) ? B1 : B1o;
    const float* w2 = (mode < 2) ? W2 : W2o;
    const float* b2 = (mode < 2) ? B2 : B2o;
    const float* w3 = (mode < 2) ? W3 : W3o;
    const float* b3 = (mode < 2) ? B3 : B3o;

    for (int idx = t; idx < 64 * 16; idx += 256) {
        int r = idx >> 4, c = (idx & 15) * 4;
        *(float4*)(s_x + r * 68 + c) =
            *(const float4*)(X + (size_t)(row0 + r) * 64 + c);
    }
    for (int idx = t; idx < 256 * 64; idx += 256) {
        int o = idx >> 6, i = idx & 63;
        s_w[i * 260 + o] = w1[idx];
    }
    __syncthreads();

    const int og = t & 31;
    const int rg = t >> 5;

    // Layer 1: 64 -> 256, relu -> s_a
    {
        float acc[8][8];
#pragma unroll
        for (int r = 0; r < 8; r++)
#pragma unroll
            for (int c = 0; c < 8; c++) acc[r][c] = 0.f;

#pragma unroll 2
        for (int i = 0; i < 64; i++) {
            float4 wA = *(const float4*)(s_w + i * 260 + og * 8);
            float4 wB = *(const float4*)(s_w + i * 260 + og * 8 + 4);
#pragma unroll
            for (int r = 0; r < 8; r++) {
                float a  = s_x[(rg * 8 + r) * 68 + i];
                float ad = dupreg(a);
                fmax2(acc[r][0], acc[r][1], a, ad, wA.x, wA.y);
                fmax2(acc[r][2], acc[r][3], a, ad, wA.z, wA.w);
                fmax2(acc[r][4], acc[r][5], a, ad, wB.x, wB.y);
                fmax2(acc[r][6], acc[r][7], a, ad, wB.z, wB.w);
            }
        }
#pragma unroll
        for (int c = 0; c < 8; c++) {
            int o = og * 8 + c;
            float bv = __ldg(b1 + o);
#pragma unroll
            for (int r = 0; r < 8; r++)
                s_a[(rg * 8 + r) * 260 + o] = fmaxf(acc[r][c] + bv, 0.f);
        }
    }

    // Layer 2: 256 -> 256, relu -> s_b
    {
        float acc[8][8];
#pragma unroll
        for (int r = 0; r < 8; r++)
#pragma unroll
            for (int c = 0; c < 8; c++) acc[r][c] = 0.f;

        for (int ch = 0; ch < 4; ch++) {
            __syncthreads();
            for (int idx = t; idx < 256 * 64; idx += 256) {
                int o = idx >> 6, i = idx & 63;
                s_w[i * 260 + o] = w2[o * 256 + ch * 64 + i];
            }
            __syncthreads();
#pragma unroll 2
            for (int i = 0; i < 64; i++) {
                float4 wA = *(const float4*)(s_w + i * 260 + og * 8);
                float4 wB = *(const float4*)(s_w + i * 260 + og * 8 + 4);
#pragma unroll
                for (int r = 0; r < 8; r++) {
                    float a  = s_a[(rg * 8 + r) * 260 + ch * 64 + i];
                    float ad = dupreg(a);
                    fmax2(acc[r][0], acc[r][1], a, ad, wA.x, wA.y);
                    fmax2(acc[r][2], acc[r][3], a, ad, wA.z, wA.w);
                    fmax2(acc[r][4], acc[r][5], a, ad, wB.x, wB.y);
                    fmax2(acc[r][6], acc[r][7], a, ad, wB.z, wB.w);
                }
            }
        }
#pragma unroll
        for (int c = 0; c < 8; c++) {
            int o = og * 8 + c;
            float bv = __ldg(b2 + o);
#pragma unroll
            for (int r = 0; r < 8; r++)
                s_b[(rg * 8 + r) * 260 + o] = fmaxf(acc[r][c] + bv, 0.f);
        }
    }

    // Layer 3: 256 -> 64 + epilogue
    {
        const int rp = t >> 3;
        const int o8 = t & 7;
        float acc3[2][8];
#pragma unroll
        for (int r = 0; r < 2; r++)
#pragma unroll
            for (int c = 0; c < 8; c++) acc3[r][c] = 0.f;

        for (int ch = 0; ch < 4; ch++) {
            __syncthreads();
            for (int idx = t; idx < 64 * 64; idx += 256) {
                int o = idx >> 6, i = idx & 63;
                s_w[i * 260 + o] = w3[o * 256 + ch * 64 + i];
            }
            __syncthreads();
#pragma unroll 4
            for (int i = 0; i < 64; i++) {
                float4 wA = *(const float4*)(s_w + i * 260 + o8 * 8);
                float4 wB = *(const float4*)(s_w + i * 260 + o8 * 8 + 4);
#pragma unroll
                for (int r = 0; r < 2; r++) {
                    float a  = s_b[(rp * 2 + r) * 260 + ch * 64 + i];
                    float ad = dupreg(a);
                    fmax2(acc3[r][0], acc3[r][1], a, ad, wA.x, wA.y);
                    fmax2(acc3[r][2], acc3[r][3], a, ad, wA.z, wA.w);
                    fmax2(acc3[r][4], acc3[r][5], a, ad, wB.x, wB.y);
                    fmax2(acc3[r][6], acc3[r][7], a, ad, wB.z, wB.w);
                }
            }
        }

        float* dst = (mode == 0) ? g_Ks : (mode == 1) ? g_Qs : g_Wo;
#pragma unroll
        for (int r = 0; r < 2; r++) {
            const int row = rp * 2 + r;
            float val[8];
            float sum = 0.f;
#pragma unroll
            for (int c = 0; c < 8; c++) {
                int o = o8 * 8 + c;
                float y = acc3[r][c] + __ldg(b3 + o);
                if (mode < 2) { val[c] = y * s_x[row * 68 + o]; sum += val[c]; }
                else          { val[c] = y; }
            }
            size_t grow = (size_t)(row0 + row);
            *(float4*)(dst + grow * 64 + o8 * 8)     = make_float4(val[0], val[1], val[2], val[3]);
            *(float4*)(dst + grow * 64 + o8 * 8 + 4) = make_float4(val[4], val[5], val[6], val[7]);
            if (mode < 2) {
                sum += __shfl_xor_sync(0xffffffffu, sum, 1);
                sum += __shfl_xor_sync(0xffffffffu, sum, 2);
                sum += __shfl_xor_sync(0xffffffffu, sum, 4);
                if (o8 == 0) ((mode == 0) ? g_sk : g_sq)[grow] = sum;
            }
        }
    }
}

// ---------------------------------------------------------------------------
// Attention, split-K. Block = 64 queries (8 warps x 8 q), key chunks of 64,
// blockIdx.z = key-range split. Grid 64x4x3 = 768 blocks -> no grid cap.
// Lane owns 2 keys for scores, dv pair {2*lane,2*lane+1} for AV.
// Emits partial (m, l, acc) per split; merge_kernel combines exactly.
// ---------------------------------------------------------------------------
#define ATT_SMEM_FLOATS (64*68 * 4 + 64 + 64)

__global__ void __launch_bounds__(256, 3) attn_kernel(
    const float* __restrict__ V)
{
    extern __shared__ float sm[];
    float* s_q  = sm;               // [64][68]  Qs tile
    float* s_k  = s_q + 64 * 68;    // [64][68]  Ks chunk
    float* s_v  = s_k + 64 * 68;    // [64][68]  V chunk
    float* s_p  = s_v + 64 * 68;    // [64][68]  probabilities (col = w*8+j)
    float* s_sk = s_p + 64 * 68;    // [64]
    float* s_sq = s_sk + 64;        // [64]

    const int t     = threadIdx.x;
    const int lane  = t & 31;
    const int w     = t >> 5;
    const int w8    = w * 8;
    const int b     = blockIdx.y;
    const int split = blockIdx.z;
    const int q0    = blockIdx.x * 64;
    const int c0    = (split * (NSEQ / 64)) / NSPLIT;        // chunk range
    const int c1    = ((split + 1) * (NSEQ / 64)) / NSPLIT;

    const float* Qs = g_Qs + (size_t)b * NSEQ * 64;
    const float* Ks = g_Ks + (size_t)b * NSEQ * 64;
    const float* Vb = V    + (size_t)b * NSEQ * 64;

    for (int idx = t; idx < 64 * 16; idx += 256) {
        int r = idx >> 4, c = (idx & 15) * 4;
        *(float4*)(s_q + r * 68 + c) = *(const float4*)(Qs + (size_t)(q0 + r) * 64 + c);
    }
    if (t < 64) s_sq[t] = g_sq[b * NSEQ + q0 + t];

    float m[8], l[8], accx[8], accy[8];
#pragma unroll
    for (int j = 0; j < 8; j++) {
        m[j] = 1e30f; l[j] = 0.f; accx[j] = 0.f; accy[j] = 0.f;
    }

    const int k0 = lane, k1 = lane + 32;

    for (int kc = c0; kc < c1; kc++) {
        __syncthreads();   // previous chunk fully consumed
        const int kb = kc * 64;
        for (int idx = t; idx < 64 * 16; idx += 256) {
            int r = idx >> 4, c = (idx & 15) * 4;
            *(float4*)(s_k + r * 68 + c) = *(const float4*)(Ks + (size_t)(kb + r) * 64 + c);
            *(float4*)(s_v + r * 68 + c) = *(const float4*)(Vb + (size_t)(kb + r) * 64 + c);
        }
        if (t < 64) s_sk[t] = g_sk[b * NSEQ + kb + t];
        __syncthreads();

        // ---- scores in two j-groups of 4 (register pressure) ----
#pragma unroll
        for (int g = 0; g < 2; g++) {
            float t0x[4], t0y[4], t1x[4], t1y[4];
#pragma unroll
            for (int j = 0; j < 4; j++) { t0x[j] = t0y[j] = t1x[j] = t1y[j] = 0.f; }

#pragma unroll 2
            for (int d = 0; d < 64; d += 4) {
                float4 a0 = *(const float4*)(s_k + k0 * 68 + d);
                float4 a1 = *(const float4*)(s_k + k1 * 68 + d);
#pragma unroll
                for (int j = 0; j < 4; j++) {
                    float4 qv = *(const float4*)(s_q + (w8 + g * 4 + j) * 68 + d);
                    addx2(t0x[j], t0y[j], fminf(a0.x, qv.x), fminf(a0.y, qv.y));
                    addx2(t0x[j], t0y[j], fminf(a0.z, qv.z), fminf(a0.w, qv.w));
                    addx2(t1x[j], t1y[j], fminf(a1.x, qv.x), fminf(a1.y, qv.y));
                    addx2(t1x[j], t1y[j], fminf(a1.z, qv.z), fminf(a1.w, qv.w));
                }
            }

            const float skk0 = s_sk[k0];
            const float skk1 = s_sk[k1];
            float p0[4], p1[4];
#pragma unroll
            for (int j = 0; j < 4; j++) {
                const int jq = g * 4 + j;
                float sqj = s_sq[w8 + jq];
                float s0 = skk0 + sqj - 2.f * (t0x[j] + t0y[j]);
                float s1 = skk1 + sqj - 2.f * (t1x[j] + t1y[j]);
                float c  = fminf(s0, s1);
#pragma unroll
                for (int off = 16; off >= 1; off >>= 1)
                    c = fminf(c, __shfl_xor_sync(0xffffffffu, c, off));
                float mn = fminf(m[jq], c);
                if (mn != m[jq]) {                 // warp-uniform branch
                    float alpha = __expf(0.5f * (mn - m[jq]) * (mn + m[jq]));
                    m[jq] = mn;
                    l[jq]    *= alpha;
                    accx[jq] *= alpha;
                    accy[jq] *= alpha;
                }
                p0[j] = __expf(0.5f * (mn - s0) * (mn + s0));
                p1[j] = __expf(0.5f * (mn - s1) * (mn + s1));
                l[jq] += p0[j] + p1[j];            // per-lane partial
            }
            *(float4*)(s_p + k0 * 68 + w8 + g * 4) = make_float4(p0[0], p0[1], p0[2], p0[3]);
            *(float4*)(s_p + k1 * 68 + w8 + g * 4) = make_float4(p1[0], p1[1], p1[2], p1[3]);
        }
        __syncwarp();

        // ---- AV: q-pair-packed accumulators, duplicated v operand ----
#pragma unroll 2
        for (int k = 0; k < 64; k++) {
            float4 pA = *(const float4*)(s_p + k * 68 + w8);
            float4 pB = *(const float4*)(s_p + k * 68 + w8 + 4);
            float2 v  = *(const float2*)(s_v + k * 68 + 2 * lane);
            float vdx = dupreg(v.x), vdy = dupreg(v.y);
            fmax2(accx[0], accx[1], pA.x, pA.y, v.x, vdx);
            fmax2(accx[2], accx[3], pA.z, pA.w, v.x, vdx);
            fmax2(accx[4], accx[5], pB.x, pB.y, v.x, vdx);
            fmax2(accx[6], accx[7], pB.z, pB.w, v.x, vdx);
            fmax2(accy[0], accy[1], pA.x, pA.y, v.y, vdy);
            fmax2(accy[2], accy[3], pA.z, pA.w, v.y, vdy);
            fmax2(accy[4], accy[5], pB.x, pB.y, v.y, vdy);
            fmax2(accy[6], accy[7], pB.z, pB.w, v.y, vdy);
        }
    }

    // epilogue: store partial (m, l, acc) for this split
#pragma unroll
    for (int j = 0; j < 8; j++) {
        float r = l[j];
#pragma unroll
        for (int off = 16; off >= 1; off >>= 1)
            r += __shfl_xor_sync(0xffffffffu, r, off);
        int row = b * NSEQ + q0 + w8 + j;
        size_t poff = (size_t)split * NROWS + row;
        *(float2*)(g_pacc + poff * 64 + 2 * lane) = make_float2(accx[j], accy[j]);
        if (lane == 0) { g_pm[poff] = m[j]; g_pl[poff] = r; }
    }
}

// ---------------------------------------------------------------------------
// Merge: combine split partials exactly, apply Wo. 1 warp per q-row.
// ---------------------------------------------------------------------------
__global__ void __launch_bounds__(256, 8) merge_kernel(float* __restrict__ out)
{
    const int t    = threadIdx.x;
    const int row  = blockIdx.x * 8 + (t >> 5);
    const int lane = t & 31;

    float mv[NSPLIT], lv[NSPLIT];
    float mm = 1e30f;
#pragma unroll
    for (int s = 0; s < NSPLIT; s++) {
        mv[s] = g_pm[(size_t)s * NROWS + row];
        lv[s] = g_pl[(size_t)s * NROWS + row];
        mm = fminf(mm, mv[s]);
    }
    float wgt[NSPLIT];
    float lsum = 0.f;
#pragma unroll
    for (int s = 0; s < NSPLIT; s++) {
        wgt[s] = __expf(0.5f * (mm - mv[s]) * (mm + mv[s]));
        lsum += wgt[s] * lv[s];
    }
    float inv = 1.0f / lsum;

    size_t o = (size_t)row * 64 + 2 * lane;
    float ax = 0.f, ay = 0.f;
#pragma unroll
    for (int s = 0; s < NSPLIT; s++) {
        float2 a = *(const float2*)(g_pacc + ((size_t)s * NROWS + row) * 64 + 2 * lane);
        ax += wgt[s] * a.x;
        ay += wgt[s] * a.y;
    }
    float2 wv = *(const float2*)(g_Wo + o);
    float2 r;
    r.x = ax * inv * wv.x;
    r.y = ay * inv * wv.y;
    *(float2*)(out + o) = r;
}

// ---------------------------------------------------------------------------
extern "C" void kernel_launch(void* const* d_in, const int* in_sizes, int n_in,
                              void* d_out, int out_size)
{
    (void)in_sizes; (void)n_in; (void)out_size;
    const float* KEY   = (const float*)d_in[0];
    const float* VALUE = (const float*)d_in[1];
    const float* QUERY = (const float*)d_in[2];
    const float* W1w = (const float*)d_in[3],  *W1b = (const float*)d_in[4];
    const float* W2w = (const float*)d_in[5],  *W2b = (const float*)d_in[6];
    const float* W3w = (const float*)d_in[7],  *W3b = (const float*)d_in[8];
    const float* O1w = (const float*)d_in[9],  *O1b = (const float*)d_in[10];
    const float* O2w = (const float*)d_in[11], *O2b = (const float*)d_in[12];
    const float* O3w = (const float*)d_in[13], *O3b = (const float*)d_in[14];

    cudaFuncSetAttribute(mlp_kernel, cudaFuncAttributeMaxDynamicSharedMemorySize,
                         MLP_SMEM_FLOATS * sizeof(float));
    cudaFuncSetAttribute(attn_kernel, cudaFuncAttributeMaxDynamicSharedMemorySize,
                         ATT_SMEM_FLOATS * sizeof(float));

    dim3 mlp_grid(NROWS / 64, 3);
    mlp_kernel<<<mlp_grid, 256, MLP_SMEM_FLOATS * sizeof(float)>>>(
        KEY, QUERY, W1w, W1b, W2w, W2b, W3w, W3b,
        O1w, O1b, O2w, O2b, O3w, O3b);

    dim3 att_grid(NSEQ / 64, NB, NSPLIT);
    attn_kernel<<<att_grid, 256, ATT_SMEM_FLOATS * sizeof(float)>>>(VALUE);

    merge_kernel<<<NROWS / 8, 256>>>((float*)d_out);
}

// round 14
// speedup vs baseline: 1.0852x; 1.0415x over previous
#include <cuda_runtime.h>
#include <cuda_bf16.h>

// B=4, N=4096, D=64, H=256.
// out[b,q,dv] = (softmax_k( -0.5*cdistL1(Ks,Qs)^2 ) @ V) * Wo
//   Ks = KEY*mlp(KEY), Qs = QUERY*mlp(QUERY), Wo = mlpo(QUERY)
// L1 dist(k,q) = sk[k] + sq[q] - 2*sum_d min(Ks,Qs); flash softmax tracks min score.
// Split-K attention; weights pre-transposed for conflict-free staging.

#define NB   4
#define NSEQ 4096
#define DD   64
#define NROWS (NB * NSEQ)
#define NSPLIT 3

__device__ float g_Ks[NROWS * DD];
__device__ float g_Qs[NROWS * DD];
__device__ float g_Wo[NROWS * DD];
__device__ float g_sk[NROWS];
__device__ float g_sq[NROWS];
// split-K partials
__device__ float g_pm[NSPLIT * NROWS];
__device__ float g_pl[NSPLIT * NROWS];
__device__ float g_pacc[(size_t)NSPLIT * NROWS * DD];
// transposed weights [input][output], set 0 = score MLP, set 1 = output MLP
__device__ float g_W1T[2][64 * 256];
__device__ float g_W2T[2][256 * 256];
__device__ float g_W3T[2][256 * 64];

// ---- packed fp32x2 (Blackwell FADD2/FFMA2, only reachable via PTX) ----
__device__ __forceinline__ void addx2(float& ax, float& ay, float bx, float by) {
    asm("{\n\t.reg .b64 ra, rb;\n\t"
        "mov.b64 ra, {%0, %1};\n\t"
        "mov.b64 rb, {%2, %3};\n\t"
        "add.rn.f32x2 ra, ra, rb;\n\t"
        "mov.b64 {%0, %1}, ra;\n\t}"
        : "+f"(ax), "+f"(ay) : "f"(bx), "f"(by));
}
__device__ __forceinline__ void fmax2(float& cx, float& cy, float ax, float ay,
                                      float bx, float by) {
    asm("{\n\t.reg .b64 rc, ra, rb;\n\t"
        "mov.b64 rc, {%0, %1};\n\t"
        "mov.b64 ra, {%2, %3};\n\t"
        "mov.b64 rb, {%4, %5};\n\t"
        "fma.rn.f32x2 rc, ra, rb, rc;\n\t"
        "mov.b64 {%0, %1}, rc;\n\t}"
        : "+f"(cx), "+f"(cy) : "f"(ax), "f"(ay), "f"(bx), "f"(by));
}
__device__ __forceinline__ float dupreg(float x) {
    float y;
    asm volatile("mov.f32 %0, %1;" : "=f"(y) : "f"(x));
    return y;
}

// ---------------------------------------------------------------------------
// Prep: transpose all six weight matrices once (row-major [out][in] -> [in][out]).
// ---------------------------------------------------------------------------
__global__ void __launch_bounds__(256) transpose_w_kernel(
    const float* __restrict__ W1,  const float* __restrict__ W2,
    const float* __restrict__ W3,  const float* __restrict__ W1o,
    const float* __restrict__ W2o, const float* __restrict__ W3o)
{
    int t = blockIdx.x * 256 + threadIdx.x;
    if (t < 256 * 64) {              // W1: [256][64] -> [64][256]
        int o = t >> 6, i = t & 63;
        g_W1T[0][i * 256 + o] = W1[t];
        g_W1T[1][i * 256 + o] = W1o[t];
    }
    if (t < 256 * 256) {             // W2: [256][256] -> [256][256]
        int o = t >> 8, i = t & 255;
        g_W2T[0][i * 256 + o] = W2[t];
        g_W2T[1][i * 256 + o] = W2o[t];
    }
    if (t < 64 * 256) {              // W3: [64][256] -> [256][64]
        int o = t >> 8, i = t & 255;
        g_W3T[0][i * 64 + o] = W3[t];
        g_W3T[1][i * 64 + o] = W3o[t];
    }
}

// ---------------------------------------------------------------------------
// MLP kernel. One block = 64 rows, 256 threads, occ 1 (217KB smem).
// Per-thread tile 8 rows x 8 outs. Staging via transposed weights:
// coalesced LDG.128 -> conflict-free STS.128. Hot loops unroll 4.
// mode: 0 KEY->Ks,sk ; 1 QUERY->Qs,sq ; 2 QUERY->Wo.
// ---------------------------------------------------------------------------
#define MLP_SMEM_FLOATS (64*68 + 64*260 + 64*260 + 64*260)

__global__ void __launch_bounds__(256, 1) mlp_kernel(
    const float* __restrict__ KEY, const float* __restrict__ QUERY,
    const float* __restrict__ B1,  const float* __restrict__ B2,
    const float* __restrict__ B3,  const float* __restrict__ B1o,
    const float* __restrict__ B2o, const float* __restrict__ B3o)
{
    extern __shared__ float sm[];
    float* s_x = sm;              // 64*68
    float* s_a = s_x + 64 * 68;   // 64*260
    float* s_b = s_a + 64 * 260;  // 64*260
    float* s_w = s_b + 64 * 260;  // 64*260 (weight chunk [in][out])

    const int t    = threadIdx.x;
    const int mode = blockIdx.y;
    const int row0 = blockIdx.x * 64;
    const int set  = (mode < 2) ? 0 : 1;

    const float* X   = (mode == 0) ? KEY : QUERY;
    const float* w1t = g_W1T[set];
    const float* w2t = g_W2T[set];
    const float* w3t = g_W3T[set];
    const float* b1  = (mode < 2) ? B1 : B1o;
    const float* b2  = (mode < 2) ? B2 : B2o;
    const float* b3  = (mode < 2) ? B3 : B3o;

    // input tile 64x64
    for (int idx = t; idx < 64 * 16; idx += 256) {
        int r = idx >> 4, c = (idx & 15) * 4;
        *(float4*)(s_x + r * 68 + c) =
            *(const float4*)(X + (size_t)(row0 + r) * 64 + c);
    }
    // stage W1T (64 in x 256 out), coalesced + conflict-free
    for (int idx = t; idx < 64 * 64; idx += 256) {
        int i = idx >> 6, o4 = (idx & 63) * 4;
        *(float4*)(s_w + i * 260 + o4) = *(const float4*)(w1t + i * 256 + o4);
    }
    __syncthreads();

    const int og = t & 31;   // 32 out-groups of 8 outs
    const int rg = t >> 5;   // 8 row-groups of 8 rows

    // ================= Layer 1: 64 -> 256, relu -> s_a =================
    {
        float acc[8][8];
#pragma unroll
        for (int r = 0; r < 8; r++)
#pragma unroll
            for (int c = 0; c < 8; c++) acc[r][c] = 0.f;

#pragma unroll 4
        for (int i = 0; i < 64; i++) {
            float4 wA = *(const float4*)(s_w + i * 260 + og * 8);
            float4 wB = *(const float4*)(s_w + i * 260 + og * 8 + 4);
#pragma unroll
            for (int r = 0; r < 8; r++) {
                float a  = s_x[(rg * 8 + r) * 68 + i];
                float ad = dupreg(a);
                fmax2(acc[r][0], acc[r][1], a, ad, wA.x, wA.y);
                fmax2(acc[r][2], acc[r][3], a, ad, wA.z, wA.w);
                fmax2(acc[r][4], acc[r][5], a, ad, wB.x, wB.y);
                fmax2(acc[r][6], acc[r][7], a, ad, wB.z, wB.w);
            }
        }
#pragma unroll
        for (int c = 0; c < 8; c++) {
            int o = og * 8 + c;
            float bv = __ldg(b1 + o);
#pragma unroll
            for (int r = 0; r < 8; r++)
                s_a[(rg * 8 + r) * 260 + o] = fmaxf(acc[r][c] + bv, 0.f);
        }
    }

    // ================= Layer 2: 256 -> 256, relu -> s_b =================
    {
        float acc[8][8];
#pragma unroll
        for (int r = 0; r < 8; r++)
#pragma unroll
            for (int c = 0; c < 8; c++) acc[r][c] = 0.f;

        for (int ch = 0; ch < 4; ch++) {
            __syncthreads();
            for (int idx = t; idx < 64 * 64; idx += 256) {
                int i = idx >> 6, o4 = (idx & 63) * 4;
                *(float4*)(s_w + i * 260 + o4) =
                    *(const float4*)(w2t + (size_t)(ch * 64 + i) * 256 + o4);
            }
            __syncthreads();
#pragma unroll 4
            for (int i = 0; i < 64; i++) {
                float4 wA = *(const float4*)(s_w + i * 260 + og * 8);
                float4 wB = *(const float4*)(s_w + i * 260 + og * 8 + 4);
#pragma unroll
                for (int r = 0; r < 8; r++) {
                    float a  = s_a[(rg * 8 + r) * 260 + ch * 64 + i];
                    float ad = dupreg(a);
                    fmax2(acc[r][0], acc[r][1], a, ad, wA.x, wA.y);
                    fmax2(acc[r][2], acc[r][3], a, ad, wA.z, wA.w);
                    fmax2(acc[r][4], acc[r][5], a, ad, wB.x, wB.y);
                    fmax2(acc[r][6], acc[r][7], a, ad, wB.z, wB.w);
                }
            }
        }
#pragma unroll
        for (int c = 0; c < 8; c++) {
            int o = og * 8 + c;
            float bv = __ldg(b2 + o);
#pragma unroll
            for (int r = 0; r < 8; r++)
                s_b[(rg * 8 + r) * 260 + o] = fmaxf(acc[r][c] + bv, 0.f);
        }
    }

    // ================= Layer 3: 256 -> 64 + epilogue =================
    {
        const int rp = t >> 3;    // 32 row-pairs (2 rows each)
        const int o8 = t & 7;     // 8 out-groups of 8 outs
        float acc3[2][8];
#pragma unroll
        for (int r = 0; r < 2; r++)
#pragma unroll
            for (int c = 0; c < 8; c++) acc3[r][c] = 0.f;

        for (int ch = 0; ch < 4; ch++) {
            __syncthreads();
            for (int idx = t; idx < 64 * 16; idx += 256) {
                int i = idx >> 4, o4 = (idx & 15) * 4;
                *(float4*)(s_w + i * 260 + o4) =
                    *(const float4*)(w3t + (size_t)(ch * 64 + i) * 64 + o4);
            }
            __syncthreads();
#pragma unroll 4
            for (int i = 0; i < 64; i++) {
                float4 wA = *(const float4*)(s_w + i * 260 + o8 * 8);
                float4 wB = *(const float4*)(s_w + i * 260 + o8 * 8 + 4);
#pragma unroll
                for (int r = 0; r < 2; r++) {
                    float a  = s_b[(rp * 2 + r) * 260 + ch * 64 + i];
                    float ad = dupreg(a);
                    fmax2(acc3[r][0], acc3[r][1], a, ad, wA.x, wA.y);
                    fmax2(acc3[r][2], acc3[r][3], a, ad, wA.z, wA.w);
                    fmax2(acc3[r][4], acc3[r][5], a, ad, wB.x, wB.y);
                    fmax2(acc3[r][6], acc3[r][7], a, ad, wB.z, wB.w);
                }
            }
        }

        float* dst = (mode == 0) ? g_Ks : (mode == 1) ? g_Qs : g_Wo;
#pragma unroll
        for (int r = 0; r < 2; r++) {
            const int row = rp * 2 + r;
            float val[8];
            float sum = 0.f;
#pragma unroll
            for (int c = 0; c < 8; c++) {
                int o = o8 * 8 + c;
                float y = acc3[r][c] + __ldg(b3 + o);
                if (mode < 2) { val[c] = y * s_x[row * 68 + o]; sum += val[c]; }
                else          { val[c] = y; }
            }
            size_t grow = (size_t)(row0 + row);
            *(float4*)(dst + grow * 64 + o8 * 8)     = make_float4(val[0], val[1], val[2], val[3]);
            *(float4*)(dst + grow * 64 + o8 * 8 + 4) = make_float4(val[4], val[5], val[6], val[7]);
            if (mode < 2) {
                sum += __shfl_xor_sync(0xffffffffu, sum, 1);
                sum += __shfl_xor_sync(0xffffffffu, sum, 2);
                sum += __shfl_xor_sync(0xffffffffu, sum, 4);
                if (o8 == 0) ((mode == 0) ? g_sk : g_sq)[grow] = sum;
            }
        }
    }
}

// ---------------------------------------------------------------------------
// Attention, split-K (unchanged from R13). Block = 64 queries (8 warps x 8 q),
// key chunks of 64, blockIdx.z = key-range split. Grid 64x4x3 = 768 blocks.
// ---------------------------------------------------------------------------
#define ATT_SMEM_FLOATS (64*68 * 4 + 64 + 64)

__global__ void __launch_bounds__(256, 3) attn_kernel(
    const float* __restrict__ V)
{
    extern __shared__ float sm[];
    float* s_q  = sm;               // [64][68]  Qs tile
    float* s_k  = s_q + 64 * 68;    // [64][68]  Ks chunk
    float* s_v  = s_k + 64 * 68;    // [64][68]  V chunk
    float* s_p  = s_v + 64 * 68;    // [64][68]  probabilities (col = w*8+j)
    float* s_sk = s_p + 64 * 68;    // [64]
    float* s_sq = s_sk + 64;        // [64]

    const int t     = threadIdx.x;
    const int lane  = t & 31;
    const int w     = t >> 5;
    const int w8    = w * 8;
    const int b     = blockIdx.y;
    const int split = blockIdx.z;
    const int q0    = blockIdx.x * 64;
    const int c0    = (split * (NSEQ / 64)) / NSPLIT;
    const int c1    = ((split + 1) * (NSEQ / 64)) / NSPLIT;

    const float* Qs = g_Qs + (size_t)b * NSEQ * 64;
    const float* Ks = g_Ks + (size_t)b * NSEQ * 64;
    const float* Vb = V    + (size_t)b * NSEQ * 64;

    for (int idx = t; idx < 64 * 16; idx += 256) {
        int r = idx >> 4, c = (idx & 15) * 4;
        *(float4*)(s_q + r * 68 + c) = *(const float4*)(Qs + (size_t)(q0 + r) * 64 + c);
    }
    if (t < 64) s_sq[t] = g_sq[b * NSEQ + q0 + t];

    float m[8], l[8], accx[8], accy[8];
#pragma unroll
    for (int j = 0; j < 8; j++) {
        m[j] = 1e30f; l[j] = 0.f; accx[j] = 0.f; accy[j] = 0.f;
    }

    const int k0 = lane, k1 = lane + 32;

    for (int kc = c0; kc < c1; kc++) {
        __syncthreads();
        const int kb = kc * 64;
        for (int idx = t; idx < 64 * 16; idx += 256) {
            int r = idx >> 4, c = (idx & 15) * 4;
            *(float4*)(s_k + r * 68 + c) = *(const float4*)(Ks + (size_t)(kb + r) * 64 + c);
            *(float4*)(s_v + r * 68 + c) = *(const float4*)(Vb + (size_t)(kb + r) * 64 + c);
        }
        if (t < 64) s_sk[t] = g_sk[b * NSEQ + kb + t];
        __syncthreads();

#pragma unroll
        for (int g = 0; g < 2; g++) {
            float t0x[4], t0y[4], t1x[4], t1y[4];
#pragma unroll
            for (int j = 0; j < 4; j++) { t0x[j] = t0y[j] = t1x[j] = t1y[j] = 0.f; }

#pragma unroll 2
            for (int d = 0; d < 64; d += 4) {
                float4 a0 = *(const float4*)(s_k + k0 * 68 + d);
                float4 a1 = *(const float4*)(s_k + k1 * 68 + d);
#pragma unroll
                for (int j = 0; j < 4; j++) {
                    float4 qv = *(const float4*)(s_q + (w8 + g * 4 + j) * 68 + d);
                    addx2(t0x[j], t0y[j], fminf(a0.x, qv.x), fminf(a0.y, qv.y));
                    addx2(t0x[j], t0y[j], fminf(a0.z, qv.z), fminf(a0.w, qv.w));
                    addx2(t1x[j], t1y[j], fminf(a1.x, qv.x), fminf(a1.y, qv.y));
                    addx2(t1x[j], t1y[j], fminf(a1.z, qv.z), fminf(a1.w, qv.w));
                }
            }

            const float skk0 = s_sk[k0];
            const float skk1 = s_sk[k1];
            float p0[4], p1[4];
#pragma unroll
            for (int j = 0; j < 4; j++) {
                const int jq = g * 4 + j;
                float sqj = s_sq[w8 + jq];
                float s0 = skk0 + sqj - 2.f * (t0x[j] + t0y[j]);
                float s1 = skk1 + sqj - 2.f * (t1x[j] + t1y[j]);
                float c  = fminf(s0, s1);
#pragma unroll
                for (int off = 16; off >= 1; off >>= 1)
                    c = fminf(c, __shfl_xor_sync(0xffffffffu, c, off));
                float mn = fminf(m[jq], c);
                if (mn != m[jq]) {
                    float alpha = __expf(0.5f * (mn - m[jq]) * (mn + m[jq]));
                    m[jq] = mn;
                    l[jq]    *= alpha;
                    accx[jq] *= alpha;
                    accy[jq] *= alpha;
                }
                p0[j] = __expf(0.5f * (mn - s0) * (mn + s0));
                p1[j] = __expf(0.5f * (mn - s1) * (mn + s1));
                l[jq] += p0[j] + p1[j];
            }
            *(float4*)(s_p + k0 * 68 + w8 + g * 4) = make_float4(p0[0], p0[1], p0[2], p0[3]);
            *(float4*)(s_p + k1 * 68 + w8 + g * 4) = make_float4(p1[0], p1[1], p1[2], p1[3]);
        }
        __syncwarp();

#pragma unroll 2
        for (int k = 0; k < 64; k++) {
            float4 pA = *(const float4*)(s_p + k * 68 + w8);
            float4 pB = *(const float4*)(s_p + k * 68 + w8 + 4);
            float2 v  = *(const float2*)(s_v + k * 68 + 2 * lane);
            float vdx = dupreg(v.x), vdy = dupreg(v.y);
            fmax2(accx[0], accx[1], pA.x, pA.y, v.x, vdx);
            fmax2(accx[2], accx[3], pA.z, pA.w, v.x, vdx);
            fmax2(accx[4], accx[5], pB.x, pB.y, v.x, vdx);
            fmax2(accx[6], accx[7], pB.z, pB.w, v.x, vdx);
            fmax2(accy[0], accy[1], pA.x, pA.y, v.y, vdy);
            fmax2(accy[2], accy[3], pA.z, pA.w, v.y, vdy);
            fmax2(accy[4], accy[5], pB.x, pB.y, v.y, vdy);
            fmax2(accy[6], accy[7], pB.z, pB.w, v.y, vdy);
        }
    }

    // epilogue: store partial (m, l, acc) for this split
#pragma unroll
    for (int j = 0; j < 8; j++) {
        float r = l[j];
#pragma unroll
        for (int off = 16; off >= 1; off >>= 1)
            r += __shfl_xor_sync(0xffffffffu, r, off);
        int row = b * NSEQ + q0 + w8 + j;
        size_t poff = (size_t)split * NROWS + row;
        *(float2*)(g_pacc + poff * 64 + 2 * lane) = make_float2(accx[j], accy[j]);
        if (lane == 0) { g_pm[poff] = m[j]; g_pl[poff] = r; }
    }
}

// ---------------------------------------------------------------------------
// Merge: combine split partials exactly, apply Wo. 1 warp per q-row.
// ---------------------------------------------------------------------------
__global__ void __launch_bounds__(256, 8) merge_kernel(float* __restrict__ out)
{
    const int t    = threadIdx.x;
    const int row  = blockIdx.x * 8 + (t >> 5);
    const int lane = t & 31;

    float mv[NSPLIT], lv[NSPLIT];
    float mm = 1e30f;
#pragma unroll
    for (int s = 0; s < NSPLIT; s++) {
        mv[s] = g_pm[(size_t)s * NROWS + row];
        lv[s] = g_pl[(size_t)s * NROWS + row];
        mm = fminf(mm, mv[s]);
    }
    float wgt[NSPLIT];
    float lsum = 0.f;
#pragma unroll
    for (int s = 0; s < NSPLIT; s++) {
        wgt[s] = __expf(0.5f * (mm - mv[s]) * (mm + mv[s]));
        lsum += wgt[s] * lv[s];
    }
    float inv = 1.0f / lsum;

    size_t o = (size_t)row * 64 + 2 * lane;
    float ax = 0.f, ay = 0.f;
#pragma unroll
    for (int s = 0; s < NSPLIT; s++) {
        float2 a = *(const float2*)(g_pacc + ((size_t)s * NROWS + row) * 64 + 2 * lane);
        ax += wgt[s] * a.x;
        ay += wgt[s] * a.y;
    }
    float2 wv = *(const float2*)(g_Wo + o);
    float2 r;
    r.x = ax * inv * wv.x;
    r.y = ay * inv * wv.y;
    *(float2*)(out + o) = r;
}

// ---------------------------------------------------------------------------
extern "C" void kernel_launch(void* const* d_in, const int* in_sizes, int n_in,
                              void* d_out, int out_size)
{
    (void)in_sizes; (void)n_in; (void)out_size;
    const float* KEY   = (const float*)d_in[0];
    const float* VALUE = (const float*)d_in[1];
    const float* QUERY = (const float*)d_in[2];
    const float* W1w = (const float*)d_in[3],  *W1b = (const float*)d_in[4];
    const float* W2w = (const float*)d_in[5],  *W2b = (const float*)d_in[6];
    const float* W3w = (const float*)d_in[7],  *W3b = (const float*)d_in[8];
    const float* O1w = (const float*)d_in[9],  *O1b = (const float*)d_in[10];
    const float* O2w = (const float*)d_in[11], *O2b = (const float*)d_in[12];
    const float* O3w = (const float*)d_in[13], *O3b = (const float*)d_in[14];

    cudaFuncSetAttribute(mlp_kernel, cudaFuncAttributeMaxDynamicSharedMemorySize,
                         MLP_SMEM_FLOATS * sizeof(float));
    cudaFuncSetAttribute(attn_kernel, cudaFuncAttributeMaxDynamicSharedMemorySize,
                         ATT_SMEM_FLOATS * sizeof(float));

    transpose_w_kernel<<<256, 256>>>(W1w, W2w, W3w, O1w, O2w, O3w);

    dim3 mlp_grid(NROWS / 64, 3);
    mlp_kernel<<<mlp_grid, 256, MLP_SMEM_FLOATS * sizeof(float)>>>(
        KEY, QUERY, W1b, W2b, W3b, O1b, O2b, O3b);

    dim3 att_grid(NSEQ / 64, NB, NSPLIT);
    attn_kernel<<<att_grid, 256, ATT_SMEM_FLOATS * sizeof(float)>>>(VALUE);

    merge_kernel<<<NROWS / 8, 256>>>((float*)d_out);
}

// round 15
// speedup vs baseline: 1.2525x; 1.1542x over previous
#include <cuda_runtime.h>
#include <cuda_bf16.h>

// B=4, N=4096, D=64, H=256.
// out[b,q,dv] = (softmax_k( -0.5*cdistL1(Ks,Qs)^2 ) @ V) * Wo
//   Ks = KEY*mlp(KEY), Qs = QUERY*mlp(QUERY), Wo = mlpo(QUERY)
// L1 dist(k,q) = sk[k] + sq[q] - 2*sum_d min(Ks,Qs); flash softmax tracks min score.
// Split-K attention; transposed weights; MLP at occ 2 with aliased activations.

#define NB   4
#define NSEQ 4096
#define DD   64
#define NROWS (NB * NSEQ)
#define NSPLIT 3

__device__ float g_Ks[NROWS * DD];
__device__ float g_Qs[NROWS * DD];
__device__ float g_Wo[NROWS * DD];
__device__ float g_sk[NROWS];
__device__ float g_sq[NROWS];
// split-K partials
__device__ float g_pm[NSPLIT * NROWS];
__device__ float g_pl[NSPLIT * NROWS];
__device__ float g_pacc[(size_t)NSPLIT * NROWS * DD];
// transposed weights [input][output], set 0 = score MLP, set 1 = output MLP
__device__ float g_W1T[2][64 * 256];
__device__ float g_W2T[2][256 * 256];
__device__ float g_W3T[2][256 * 64];

// ---- packed fp32x2 (Blackwell FADD2/FFMA2, only reachable via PTX) ----
__device__ __forceinline__ void addx2(float& ax, float& ay, float bx, float by) {
    asm("{\n\t.reg .b64 ra, rb;\n\t"
        "mov.b64 ra, {%0, %1};\n\t"
        "mov.b64 rb, {%2, %3};\n\t"
        "add.rn.f32x2 ra, ra, rb;\n\t"
        "mov.b64 {%0, %1}, ra;\n\t}"
        : "+f"(ax), "+f"(ay) : "f"(bx), "f"(by));
}
__device__ __forceinline__ void fmax2(float& cx, float& cy, float ax, float ay,
                                      float bx, float by) {
    asm("{\n\t.reg .b64 rc, ra, rb;\n\t"
        "mov.b64 rc, {%0, %1};\n\t"
        "mov.b64 ra, {%2, %3};\n\t"
        "mov.b64 rb, {%4, %5};\n\t"
        "fma.rn.f32x2 rc, ra, rb, rc;\n\t"
        "mov.b64 {%0, %1}, rc;\n\t}"
        : "+f"(cx), "+f"(cy) : "f"(ax), "f"(ay), "f"(bx), "f"(by));
}
__device__ __forceinline__ float dupreg(float x) {
    float y;
    asm volatile("mov.f32 %0, %1;" : "=f"(y) : "f"(x));
    return y;
}

// ---------------------------------------------------------------------------
// Prep: transpose all six weight matrices once ([out][in] -> [in][out]).
// ---------------------------------------------------------------------------
__global__ void __launch_bounds__(256) transpose_w_kernel(
    const float* __restrict__ W1,  const float* __restrict__ W2,
    const float* __restrict__ W3,  const float* __restrict__ W1o,
    const float* __restrict__ W2o, const float* __restrict__ W3o)
{
    int t = blockIdx.x * 256 + threadIdx.x;
    if (t < 256 * 64) {              // W1: [256][64] -> [64][256]
        int o = t >> 6, i = t & 63;
        g_W1T[0][i * 256 + o] = W1[t];
        g_W1T[1][i * 256 + o] = W1o[t];
    }
    if (t < 256 * 256) {             // W2: [256][256] -> [256][256]
        int o = t >> 8, i = t & 255;
        g_W2T[0][i * 256 + o] = W2[t];
        g_W2T[1][i * 256 + o] = W2o[t];
    }
    if (t < 64 * 256) {              // W3: [64][256] -> [256][64]
        int o = t >> 8, i = t & 255;
        g_W3T[0][i * 64 + o] = W3[t];
        g_W3T[1][i * 64 + o] = W3o[t];
    }
}

// ---------------------------------------------------------------------------
// MLP kernel. Block = 64 rows, 256 threads, occ 2 (114.7KB smem).
// Activations aliased (h1/h2 share s_a); weights staged in 32-input chunks.
// Out-tile per thread: {lane*4..+3} and {128+lane*4..+3} -> all smem traffic
// lane-contiguous (conflict-free at stride 256).
// mode: 0 KEY->Ks,sk ; 1 QUERY->Qs,sq ; 2 QUERY->Wo.
// ---------------------------------------------------------------------------
#define MLP_SMEM_FLOATS (64*64 + 64*256 + 32*256)

__global__ void __launch_bounds__(256, 2) mlp_kernel(
    const float* __restrict__ KEY, const float* __restrict__ QUERY,
    const float* __restrict__ B1,  const float* __restrict__ B2,
    const float* __restrict__ B3,  const float* __restrict__ B1o,
    const float* __restrict__ B2o, const float* __restrict__ B3o)
{
    extern __shared__ float sm[];
    float* s_x = sm;               // 64*64  input tile
    float* s_a = s_x + 64 * 64;    // 64*256 h1, then h2 (aliased)
    float* s_w = s_a + 64 * 256;   // 32*256 weight chunk [in][out]

    const int t    = threadIdx.x;
    const int mode = blockIdx.y;
    const int row0 = blockIdx.x * 64;
    const int set  = (mode < 2) ? 0 : 1;

    const float* X   = (mode == 0) ? KEY : QUERY;
    const float* w1t = g_W1T[set];
    const float* w2t = g_W2T[set];
    const float* w3t = g_W3T[set];
    const float* b1  = (mode < 2) ? B1 : B1o;
    const float* b2  = (mode < 2) ? B2 : B2o;
    const float* b3  = (mode < 2) ? B3 : B3o;

    // input tile 64x64 (stride 64; reads later are warp-uniform broadcasts)
    for (int idx = t; idx < 64 * 16; idx += 256) {
        int r = idx >> 4, c = (idx & 15) * 4;
        *(float4*)(s_x + r * 64 + c) =
            *(const float4*)(X + (size_t)(row0 + r) * 64 + c);
    }

    const int l4 = (t & 31) * 4;   // first out group: lane*4 (second: +128)
    const int rg = t >> 5;         // 8 row-groups of 8 rows (one per warp)

    // ================= Layer 1: 64 -> 256, relu -> s_a =================
    {
        float acc[8][8];
#pragma unroll
        for (int r = 0; r < 8; r++)
#pragma unroll
            for (int c = 0; c < 8; c++) acc[r][c] = 0.f;

        for (int ch = 0; ch < 2; ch++) {
            __syncthreads();
            for (int idx = t; idx < 32 * 64; idx += 256) {
                int i = idx >> 6, o4 = (idx & 63) * 4;
                *(float4*)(s_w + i * 256 + o4) =
                    *(const float4*)(w1t + (size_t)(ch * 32 + i) * 256 + o4);
            }
            __syncthreads();
#pragma unroll 4
            for (int i = 0; i < 32; i++) {
                float4 wA = *(const float4*)(s_w + i * 256 + l4);
                float4 wB = *(const float4*)(s_w + i * 256 + 128 + l4);
#pragma unroll
                for (int r = 0; r < 8; r++) {
                    float a  = s_x[(rg * 8 + r) * 64 + ch * 32 + i];
                    float ad = dupreg(a);
                    fmax2(acc[r][0], acc[r][1], a, ad, wA.x, wA.y);
                    fmax2(acc[r][2], acc[r][3], a, ad, wA.z, wA.w);
                    fmax2(acc[r][4], acc[r][5], a, ad, wB.x, wB.y);
                    fmax2(acc[r][6], acc[r][7], a, ad, wB.z, wB.w);
                }
            }
        }
        float4 bA = *(const float4*)(b1 + l4);
        float4 bB = *(const float4*)(b1 + 128 + l4);
#pragma unroll
        for (int r = 0; r < 8; r++) {
            int row = rg * 8 + r;
            *(float4*)(s_a + row * 256 + l4) = make_float4(
                fmaxf(acc[r][0] + bA.x, 0.f), fmaxf(acc[r][1] + bA.y, 0.f),
                fmaxf(acc[r][2] + bA.z, 0.f), fmaxf(acc[r][3] + bA.w, 0.f));
            *(float4*)(s_a + row * 256 + 128 + l4) = make_float4(
                fmaxf(acc[r][4] + bB.x, 0.f), fmaxf(acc[r][5] + bB.y, 0.f),
                fmaxf(acc[r][6] + bB.z, 0.f), fmaxf(acc[r][7] + bB.w, 0.f));
        }
    }

    // ================= Layer 2: 256 -> 256, relu -> s_a (aliased) =======
    {
        float acc[8][8];
#pragma unroll
        for (int r = 0; r < 8; r++)
#pragma unroll
            for (int c = 0; c < 8; c++) acc[r][c] = 0.f;

        for (int ch = 0; ch < 8; ch++) {
            __syncthreads();   // prior s_w reads done; s_a writes visible
            for (int idx = t; idx < 32 * 64; idx += 256) {
                int i = idx >> 6, o4 = (idx & 63) * 4;
                *(float4*)(s_w + i * 256 + o4) =
                    *(const float4*)(w2t + (size_t)(ch * 32 + i) * 256 + o4);
            }
            __syncthreads();
#pragma unroll 4
            for (int i = 0; i < 32; i++) {
                float4 wA = *(const float4*)(s_w + i * 256 + l4);
                float4 wB = *(const float4*)(s_w + i * 256 + 128 + l4);
#pragma unroll
                for (int r = 0; r < 8; r++) {
                    float a  = s_a[(rg * 8 + r) * 256 + ch * 32 + i];
                    float ad = dupreg(a);
                    fmax2(acc[r][0], acc[r][1], a, ad, wA.x, wA.y);
                    fmax2(acc[r][2], acc[r][3], a, ad, wA.z, wA.w);
                    fmax2(acc[r][4], acc[r][5], a, ad, wB.x, wB.y);
                    fmax2(acc[r][6], acc[r][7], a, ad, wB.z, wB.w);
                }
            }
        }
        __syncthreads();   // all h1 reads complete before overwrite
        float4 bA = *(const float4*)(b2 + l4);
        float4 bB = *(const float4*)(b2 + 128 + l4);
#pragma unroll
        for (int r = 0; r < 8; r++) {
            int row = rg * 8 + r;
            *(float4*)(s_a + row * 256 + l4) = make_float4(
                fmaxf(acc[r][0] + bA.x, 0.f), fmaxf(acc[r][1] + bA.y, 0.f),
                fmaxf(acc[r][2] + bA.z, 0.f), fmaxf(acc[r][3] + bA.w, 0.f));
            *(float4*)(s_a + row * 256 + 128 + l4) = make_float4(
                fmaxf(acc[r][4] + bB.x, 0.f), fmaxf(acc[r][5] + bB.y, 0.f),
                fmaxf(acc[r][6] + bB.z, 0.f), fmaxf(acc[r][7] + bB.w, 0.f));
        }
    }

    // ================= Layer 3: 256 -> 64 + epilogue =================
    {
        const int l2 = (t & 31) * 2;   // 2 outs per thread (lane-contiguous)
        float ax[8], ay[8];
#pragma unroll
        for (int r = 0; r < 8; r++) { ax[r] = 0.f; ay[r] = 0.f; }

        for (int ch = 0; ch < 4; ch++) {
            __syncthreads();
            for (int idx = t; idx < 64 * 16; idx += 256) {
                int i = idx >> 4, o4 = (idx & 15) * 4;
                *(float4*)(s_w + i * 64 + o4) =
                    *(const float4*)(w3t + (size_t)(ch * 64 + i) * 64 + o4);
            }
            __syncthreads();
#pragma unroll 4
            for (int i = 0; i < 64; i++) {
                float2 wv = *(const float2*)(s_w + i * 64 + l2);
#pragma unroll
                for (int r = 0; r < 8; r++) {
                    float a  = s_a[(rg * 8 + r) * 256 + ch * 64 + i];
                    float ad = dupreg(a);
                    fmax2(ax[r], ay[r], a, ad, wv.x, wv.y);
                }
            }
        }

        float* dst = (mode == 0) ? g_Ks : (mode == 1) ? g_Qs : g_Wo;
        float2 bv = *(const float2*)(b3 + l2);
#pragma unroll
        for (int r = 0; r < 8; r++) {
            const int row = rg * 8 + r;
            float y0 = ax[r] + bv.x;
            float y1 = ay[r] + bv.y;
            float v0, v1;
            if (mode < 2) {
                float2 xv = *(const float2*)(s_x + row * 64 + l2);
                v0 = y0 * xv.x; v1 = y1 * xv.y;
            } else {
                v0 = y0; v1 = y1;
            }
            size_t grow = (size_t)(row0 + row);
            *(float2*)(dst + grow * 64 + l2) = make_float2(v0, v1);
            if (mode < 2) {
                float sum = v0 + v1;
#pragma unroll
                for (int off = 16; off >= 1; off >>= 1)
                    sum += __shfl_xor_sync(0xffffffffu, sum, off);
                if ((t & 31) == 0) ((mode == 0) ? g_sk : g_sq)[grow] = sum;
            }
        }
    }
}

// ---------------------------------------------------------------------------
// Attention, split-K (unchanged). Block = 64 queries (8 warps x 8 q),
// key chunks of 64, blockIdx.z = split. Grid 64x4x3 = 768 blocks, occ 3.
// ---------------------------------------------------------------------------
#define ATT_SMEM_FLOATS (64*68 * 4 + 64 + 64)

__global__ void __launch_bounds__(256, 3) attn_kernel(
    const float* __restrict__ V)
{
    extern __shared__ float sm[];
    float* s_q  = sm;               // [64][68]
    float* s_k  = s_q + 64 * 68;    // [64][68]
    float* s_v  = s_k + 64 * 68;    // [64][68]
    float* s_p  = s_v + 64 * 68;    // [64][68]
    float* s_sk = s_p + 64 * 68;    // [64]
    float* s_sq = s_sk + 64;        // [64]

    const int t     = threadIdx.x;
    const int lane  = t & 31;
    const int w     = t >> 5;
    const int w8    = w * 8;
    const int b     = blockIdx.y;
    const int split = blockIdx.z;
    const int q0    = blockIdx.x * 64;
    const int c0    = (split * (NSEQ / 64)) / NSPLIT;
    const int c1    = ((split + 1) * (NSEQ / 64)) / NSPLIT;

    const float* Qs = g_Qs + (size_t)b * NSEQ * 64;
    const float* Ks = g_Ks + (size_t)b * NSEQ * 64;
    const float* Vb = V    + (size_t)b * NSEQ * 64;

    for (int idx = t; idx < 64 * 16; idx += 256) {
        int r = idx >> 4, c = (idx & 15) * 4;
        *(float4*)(s_q + r * 68 + c) = *(const float4*)(Qs + (size_t)(q0 + r) * 64 + c);
    }
    if (t < 64) s_sq[t] = g_sq[b * NSEQ + q0 + t];

    float m[8], l[8], accx[8], accy[8];
#pragma unroll
    for (int j = 0; j < 8; j++) {
        m[j] = 1e30f; l[j] = 0.f; accx[j] = 0.f; accy[j] = 0.f;
    }

    const int k0 = lane, k1 = lane + 32;

    for (int kc = c0; kc < c1; kc++) {
        __syncthreads();
        const int kb = kc * 64;
        for (int idx = t; idx < 64 * 16; idx += 256) {
            int r = idx >> 4, c = (idx & 15) * 4;
            *(float4*)(s_k + r * 68 + c) = *(const float4*)(Ks + (size_t)(kb + r) * 64 + c);
            *(float4*)(s_v + r * 68 + c) = *(const float4*)(Vb + (size_t)(kb + r) * 64 + c);
        }
        if (t < 64) s_sk[t] = g_sk[b * NSEQ + kb + t];
        __syncthreads();

#pragma unroll
        for (int g = 0; g < 2; g++) {
            float t0x[4], t0y[4], t1x[4], t1y[4];
#pragma unroll
            for (int j = 0; j < 4; j++) { t0x[j] = t0y[j] = t1x[j] = t1y[j] = 0.f; }

#pragma unroll 2
            for (int d = 0; d < 64; d += 4) {
                float4 a0 = *(const float4*)(s_k + k0 * 68 + d);
                float4 a1 = *(const float4*)(s_k + k1 * 68 + d);
#pragma unroll
                for (int j = 0; j < 4; j++) {
                    float4 qv = *(const float4*)(s_q + (w8 + g * 4 + j) * 68 + d);
                    addx2(t0x[j], t0y[j], fminf(a0.x, qv.x), fminf(a0.y, qv.y));
                    addx2(t0x[j], t0y[j], fminf(a0.z, qv.z), fminf(a0.w, qv.w));
                    addx2(t1x[j], t1y[j], fminf(a1.x, qv.x), fminf(a1.y, qv.y));
                    addx2(t1x[j], t1y[j], fminf(a1.z, qv.z), fminf(a1.w, qv.w));
                }
            }

            const float skk0 = s_sk[k0];
            const float skk1 = s_sk[k1];
            float p0[4], p1[4];
#pragma unroll
            for (int j = 0; j < 4; j++) {
                const int jq = g * 4 + j;
                float sqj = s_sq[w8 + jq];
                float s0 = skk0 + sqj - 2.f * (t0x[j] + t0y[j]);
                float s1 = skk1 + sqj - 2.f * (t1x[j] + t1y[j]);
                float c  = fminf(s0, s1);
#pragma unroll
                for (int off = 16; off >= 1; off >>= 1)
                    c = fminf(c, __shfl_xor_sync(0xffffffffu, c, off));
                float mn = fminf(m[jq], c);
                if (mn != m[jq]) {
                    float alpha = __expf(0.5f * (mn - m[jq]) * (mn + m[jq]));
                    m[jq] = mn;
                    l[jq]    *= alpha;
                    accx[jq] *= alpha;
                    accy[jq] *= alpha;
                }
                p0[j] = __expf(0.5f * (mn - s0) * (mn + s0));
                p1[j] = __expf(0.5f * (mn - s1) * (mn + s1));
                l[jq] += p0[j] + p1[j];
            }
            *(float4*)(s_p + k0 * 68 + w8 + g * 4) = make_float4(p0[0], p0[1], p0[2], p0[3]);
            *(float4*)(s_p + k1 * 68 + w8 + g * 4) = make_float4(p1[0], p1[1], p1[2], p1[3]);
        }
        __syncwarp();

#pragma unroll 2
        for (int k = 0; k < 64; k++) {
            float4 pA = *(const float4*)(s_p + k * 68 + w8);
            float4 pB = *(const float4*)(s_p + k * 68 + w8 + 4);
            float2 v  = *(const float2*)(s_v + k * 68 + 2 * lane);
            float vdx = dupreg(v.x), vdy = dupreg(v.y);
            fmax2(accx[0], accx[1], pA.x, pA.y, v.x, vdx);
            fmax2(accx[2], accx[3], pA.z, pA.w, v.x, vdx);
            fmax2(accx[4], accx[5], pB.x, pB.y, v.x, vdx);
            fmax2(accx[6], accx[7], pB.z, pB.w, v.x, vdx);
            fmax2(accy[0], accy[1], pA.x, pA.y, v.y, vdy);
            fmax2(accy[2], accy[3], pA.z, pA.w, v.y, vdy);
            fmax2(accy[4], accy[5], pB.x, pB.y, v.y, vdy);
            fmax2(accy[6], accy[7], pB.z, pB.w, v.y, vdy);
        }
    }

    // epilogue: store partial (m, l, acc) for this split
#pragma unroll
    for (int j = 0; j < 8; j++) {
        float r = l[j];
#pragma unroll
        for (int off = 16; off >= 1; off >>= 1)
            r += __shfl_xor_sync(0xffffffffu, r, off);
        int row = b * NSEQ + q0 + w8 + j;
        size_t poff = (size_t)split * NROWS + row;
        *(float2*)(g_pacc + poff * 64 + 2 * lane) = make_float2(accx[j], accy[j]);
        if (lane == 0) { g_pm[poff] = m[j]; g_pl[poff] = r; }
    }
}

// ---------------------------------------------------------------------------
// Merge: combine split partials exactly, apply Wo. 1 warp per q-row.
// ---------------------------------------------------------------------------
__global__ void __launch_bounds__(256, 8) merge_kernel(float* __restrict__ out)
{
    const int t    = threadIdx.x;
    const int row  = blockIdx.x * 8 + (t >> 5);
    const int lane = t & 31;

    float mv[NSPLIT], lv[NSPLIT];
    float mm = 1e30f;
#pragma unroll
    for (int s = 0; s < NSPLIT; s++) {
        mv[s] = g_pm[(size_t)s * NROWS + row];
        lv[s] = g_pl[(size_t)s * NROWS + row];
        mm = fminf(mm, mv[s]);
    }
    float wgt[NSPLIT];
    float lsum = 0.f;
#pragma unroll
    for (int s = 0; s < NSPLIT; s++) {
        wgt[s] = __expf(0.5f * (mm - mv[s]) * (mm + mv[s]));
        lsum += wgt[s] * lv[s];
    }
    float inv = 1.0f / lsum;

    size_t o = (size_t)row * 64 + 2 * lane;
    float ax = 0.f, ay = 0.f;
#pragma unroll
    for (int s = 0; s < NSPLIT; s++) {
        float2 a = *(const float2*)(g_pacc + ((size_t)s * NROWS + row) * 64 + 2 * lane);
        ax += wgt[s] * a.x;
        ay += wgt[s] * a.y;
    }
    float2 wv = *(const float2*)(g_Wo + o);
    float2 r;
    r.x = ax * inv * wv.x;
    r.y = ay * inv * wv.y;
    *(float2*)(out + o) = r;
}

// ---------------------------------------------------------------------------
extern "C" void kernel_launch(void* const* d_in, const int* in_sizes, int n_in,
                              void* d_out, int out_size)
{
    (void)in_sizes; (void)n_in; (void)out_size;
    const float* KEY   = (const float*)d_in[0];
    const float* VALUE = (const float*)d_in[1];
    const float* QUERY = (const float*)d_in[2];
    const float* W1w = (const float*)d_in[3],  *W1b = (const float*)d_in[4];
    const float* W2w = (const float*)d_in[5],  *W2b = (const float*)d_in[6];
    const float* W3w = (const float*)d_in[7],  *W3b = (const float*)d_in[8];
    const float* O1w = (const float*)d_in[9],  *O1b = (const float*)d_in[10];
    const float* O2w = (const float*)d_in[11], *O2b = (const float*)d_in[12];
    const float* O3w = (const float*)d_in[13], *O3b = (const float*)d_in[14];

    cudaFuncSetAttribute(mlp_kernel, cudaFuncAttributeMaxDynamicSharedMemorySize,
                         MLP_SMEM_FLOATS * sizeof(float));
    cudaFuncSetAttribute(attn_kernel, cudaFuncAttributeMaxDynamicSharedMemorySize,
                         ATT_SMEM_FLOATS * sizeof(float));

    transpose_w_kernel<<<256, 256>>>(W1w, W2w, W3w, O1w, O2w, O3w);

    dim3 mlp_grid(NROWS / 64, 3);
    mlp_kernel<<<mlp_grid, 256, MLP_SMEM_FLOATS * sizeof(float)>>>(
        KEY, QUERY, W1b, W2b, W3b, O1b, O2b, O3b);

    dim3 att_grid(NSEQ / 64, NB, NSPLIT);
    attn_kernel<<<att_grid, 256, ATT_SMEM_FLOATS * sizeof(float)>>>(VALUE);

    merge_kernel<<<NROWS / 8, 256>>>((float*)d_out);
}

// round 17
// speedup vs baseline: 1.3716x; 1.0951x over previous
#include <cuda_runtime.h>
#include <cuda_bf16.h>

// B=4, N=4096, D=64, H=256.
// out[b,q,dv] = (softmax_k( -0.5*cdistL1(Ks,Qs)^2 ) @ V) * Wo
//   Ks = KEY*mlp(KEY), Qs = QUERY*mlp(QUERY), Wo = mlpo(QUERY)
// L1 dist(k,q) = sk[k] + sq[q] - 2*sum_d min(Ks,Qs); flash softmax tracks min score.
// Split-K attention (NSPLIT=5 for wave balance); Wo-MLP fused into the attention
// launch as a second block role (fills attention wave-tail idle slots).

#define NB   4
#define NSEQ 4096
#define DD   64
#define NROWS (NB * NSEQ)
#define NSPLIT 5
#define ATT_BLOCKS (NB * NSPLIT * (NSEQ / 64))   // 1280
#define WO_BLOCKS  (NROWS / 32)                  // 512

__device__ float g_Ks[NROWS * DD];
__device__ float g_Qs[NROWS * DD];
__device__ float g_Wo[NROWS * DD];
__device__ float g_sk[NROWS];
__device__ float g_sq[NROWS];
// split-K partials
__device__ float g_pm[NSPLIT * NROWS];
__device__ float g_pl[NSPLIT * NROWS];
__device__ float g_pacc[(size_t)NSPLIT * NROWS * DD];
// transposed weights [input][output], set 0 = score MLP, set 1 = output MLP
__device__ float g_W1T[2][64 * 256];
__device__ float g_W2T[2][256 * 256];
__device__ float g_W3T[2][256 * 64];

// ---- packed fp32x2 (Blackwell FADD2/FFMA2, only reachable via PTX) ----
__device__ __forceinline__ void addx2(float& ax, float& ay, float bx, float by) {
    asm("{\n\t.reg .b64 ra, rb;\n\t"
        "mov.b64 ra, {%0, %1};\n\t"
        "mov.b64 rb, {%2, %3};\n\t"
        "add.rn.f32x2 ra, ra, rb;\n\t"
        "mov.b64 {%0, %1}, ra;\n\t}"
        : "+f"(ax), "+f"(ay) : "f"(bx), "f"(by));
}
__device__ __forceinline__ void fmax2(float& cx, float& cy, float ax, float ay,
                                      float bx, float by) {
    asm("{\n\t.reg .b64 rc, ra, rb;\n\t"
        "mov.b64 rc, {%0, %1};\n\t"
        "mov.b64 ra, {%2, %3};\n\t"
        "mov.b64 rb, {%4, %5};\n\t"
        "fma.rn.f32x2 rc, ra, rb, rc;\n\t"
        "mov.b64 {%0, %1}, rc;\n\t}"
        : "+f"(cx), "+f"(cy) : "f"(ax), "f"(ay), "f"(bx), "f"(by));
}
__device__ __forceinline__ float dupreg(float x) {
    float y;
    asm volatile("mov.f32 %0, %1;" : "=f"(y) : "f"(x));
    return y;
}

// ---------------------------------------------------------------------------
// Prep: transpose all six weight matrices once ([out][in] -> [in][out]).
// ---------------------------------------------------------------------------
__global__ void __launch_bounds__(256) transpose_w_kernel(
    const float* __restrict__ W1,  const float* __restrict__ W2,
    const float* __restrict__ W3,  const float* __restrict__ W1o,
    const float* __restrict__ W2o, const float* __restrict__ W3o)
{
    int t = blockIdx.x * 256 + threadIdx.x;
    if (t < 256 * 64) {              // W1: [256][64] -> [64][256]
        int o = t >> 6, i = t & 63;
        g_W1T[0][i * 256 + o] = W1[t];
        g_W1T[1][i * 256 + o] = W1o[t];
    }
    if (t < 256 * 256) {             // W2: [256][256] -> [256][256]
        int o = t >> 8, i = t & 255;
        g_W2T[0][i * 256 + o] = W2[t];
        g_W2T[1][i * 256 + o] = W2o[t];
    }
    if (t < 64 * 256) {              // W3: [64][256] -> [256][64]
        int o = t >> 8, i = t & 255;
        g_W3T[0][i * 64 + o] = W3[t];
        g_W3T[1][i * 64 + o] = W3o[t];
    }
}

// ---------------------------------------------------------------------------
// MLP kernel, modes 0 (KEY->Ks,sk) and 1 (QUERY->Qs,sq) only.
// Block = 64 rows, 256 threads, occ 2 (114.7KB smem).
// ---------------------------------------------------------------------------
#define MLP_SMEM_FLOATS (64*64 + 64*256 + 32*256)

__global__ void __launch_bounds__(256, 2) mlp_kernel(
    const float* __restrict__ KEY, const float* __restrict__ QUERY,
    const float* __restrict__ B1,  const float* __restrict__ B2,
    const float* __restrict__ B3)
{
    extern __shared__ float sm[];
    float* s_x = sm;               // 64*64  input tile
    float* s_a = s_x + 64 * 64;    // 64*256 h1, then h2 (aliased)
    float* s_w = s_a + 64 * 256;   // 32*256 weight chunk [in][out]

    const int t    = threadIdx.x;
    const int mode = blockIdx.y;
    const int row0 = blockIdx.x * 64;

    const float* X   = (mode == 0) ? KEY : QUERY;
    const float* w1t = g_W1T[0];
    const float* w2t = g_W2T[0];
    const float* w3t = g_W3T[0];

    for (int idx = t; idx < 64 * 16; idx += 256) {
        int r = idx >> 4, c = (idx & 15) * 4;
        *(float4*)(s_x + r * 64 + c) =
            *(const float4*)(X + (size_t)(row0 + r) * 64 + c);
    }

    const int l4 = (t & 31) * 4;
    const int rg = t >> 5;

    // Layer 1: 64 -> 256, relu -> s_a
    {
        float acc[8][8];
#pragma unroll
        for (int r = 0; r < 8; r++)
#pragma unroll
            for (int c = 0; c < 8; c++) acc[r][c] = 0.f;

        for (int ch = 0; ch < 2; ch++) {
            __syncthreads();
            for (int idx = t; idx < 32 * 64; idx += 256) {
                int i = idx >> 6, o4 = (idx & 63) * 4;
                *(float4*)(s_w + i * 256 + o4) =
                    *(const float4*)(w1t + (size_t)(ch * 32 + i) * 256 + o4);
            }
            __syncthreads();
#pragma unroll 4
            for (int i = 0; i < 32; i++) {
                float4 wA = *(const float4*)(s_w + i * 256 + l4);
                float4 wB = *(const float4*)(s_w + i * 256 + 128 + l4);
#pragma unroll
                for (int r = 0; r < 8; r++) {
                    float a  = s_x[(rg * 8 + r) * 64 + ch * 32 + i];
                    float ad = dupreg(a);
                    fmax2(acc[r][0], acc[r][1], a, ad, wA.x, wA.y);
                    fmax2(acc[r][2], acc[r][3], a, ad, wA.z, wA.w);
                    fmax2(acc[r][4], acc[r][5], a, ad, wB.x, wB.y);
                    fmax2(acc[r][6], acc[r][7], a, ad, wB.z, wB.w);
                }
            }
        }
        float4 bA = *(const float4*)(B1 + l4);
        float4 bB = *(const float4*)(B1 + 128 + l4);
#pragma unroll
        for (int r = 0; r < 8; r++) {
            int row = rg * 8 + r;
            *(float4*)(s_a + row * 256 + l4) = make_float4(
                fmaxf(acc[r][0] + bA.x, 0.f), fmaxf(acc[r][1] + bA.y, 0.f),
                fmaxf(acc[r][2] + bA.z, 0.f), fmaxf(acc[r][3] + bA.w, 0.f));
            *(float4*)(s_a + row * 256 + 128 + l4) = make_float4(
                fmaxf(acc[r][4] + bB.x, 0.f), fmaxf(acc[r][5] + bB.y, 0.f),
                fmaxf(acc[r][6] + bB.z, 0.f), fmaxf(acc[r][7] + bB.w, 0.f));
        }
    }

    // Layer 2: 256 -> 256, relu -> s_a (aliased)
    {
        float acc[8][8];
#pragma unroll
        for (int r = 0; r < 8; r++)
#pragma unroll
            for (int c = 0; c < 8; c++) acc[r][c] = 0.f;

        for (int ch = 0; ch < 8; ch++) {
            __syncthreads();
            for (int idx = t; idx < 32 * 64; idx += 256) {
                int i = idx >> 6, o4 = (idx & 63) * 4;
                *(float4*)(s_w + i * 256 + o4) =
                    *(const float4*)(w2t + (size_t)(ch * 32 + i) * 256 + o4);
            }
            __syncthreads();
#pragma unroll 4
            for (int i = 0; i < 32; i++) {
                float4 wA = *(const float4*)(s_w + i * 256 + l4);
                float4 wB = *(const float4*)(s_w + i * 256 + 128 + l4);
#pragma unroll
                for (int r = 0; r < 8; r++) {
                    float a  = s_a[(rg * 8 + r) * 256 + ch * 32 + i];
                    float ad = dupreg(a);
                    fmax2(acc[r][0], acc[r][1], a, ad, wA.x, wA.y);
                    fmax2(acc[r][2], acc[r][3], a, ad, wA.z, wA.w);
                    fmax2(acc[r][4], acc[r][5], a, ad, wB.x, wB.y);
                    fmax2(acc[r][6], acc[r][7], a, ad, wB.z, wB.w);
                }
            }
        }
        __syncthreads();
        float4 bA = *(const float4*)(B2 + l4);
        float4 bB = *(const float4*)(B2 + 128 + l4);
#pragma unroll
        for (int r = 0; r < 8; r++) {
            int row = rg * 8 + r;
            *(float4*)(s_a + row * 256 + l4) = make_float4(
                fmaxf(acc[r][0] + bA.x, 0.f), fmaxf(acc[r][1] + bA.y, 0.f),
                fmaxf(acc[r][2] + bA.z, 0.f), fmaxf(acc[r][3] + bA.w, 0.f));
            *(float4*)(s_a + row * 256 + 128 + l4) = make_float4(
                fmaxf(acc[r][4] + bB.x, 0.f), fmaxf(acc[r][5] + bB.y, 0.f),
                fmaxf(acc[r][6] + bB.z, 0.f), fmaxf(acc[r][7] + bB.w, 0.f));
        }
    }

    // Layer 3: 256 -> 64 + epilogue (scale by input, row sums)
    {
        const int l2 = (t & 31) * 2;
        float ax[8], ay[8];
#pragma unroll
        for (int r = 0; r < 8; r++) { ax[r] = 0.f; ay[r] = 0.f; }

        for (int ch = 0; ch < 4; ch++) {
            __syncthreads();
            for (int idx = t; idx < 64 * 16; idx += 256) {
                int i = idx >> 4, o4 = (idx & 15) * 4;
                *(float4*)(s_w + i * 64 + o4) =
                    *(const float4*)(w3t + (size_t)(ch * 64 + i) * 64 + o4);
            }
            __syncthreads();
#pragma unroll 4
            for (int i = 0; i < 64; i++) {
                float2 wv = *(const float2*)(s_w + i * 64 + l2);
#pragma unroll
                for (int r = 0; r < 8; r++) {
                    float a  = s_a[(rg * 8 + r) * 256 + ch * 64 + i];
                    float ad = dupreg(a);
                    fmax2(ax[r], ay[r], a, ad, wv.x, wv.y);
                }
            }
        }

        float* dst = (mode == 0) ? g_Ks : g_Qs;
        float2 bv = *(const float2*)(B3 + l2);
#pragma unroll
        for (int r = 0; r < 8; r++) {
            const int row = rg * 8 + r;
            float y0 = ax[r] + bv.x;
            float y1 = ay[r] + bv.y;
            float2 xv = *(const float2*)(s_x + row * 64 + l2);
            float v0 = y0 * xv.x, v1 = y1 * xv.y;
            size_t grow = (size_t)(row0 + row);
            *(float2*)(dst + grow * 64 + l2) = make_float2(v0, v1);
            float sum = v0 + v1;
#pragma unroll
            for (int off = 16; off >= 1; off >>= 1)
                sum += __shfl_xor_sync(0xffffffffu, sum, off);
            if ((t & 31) == 0) ((mode == 0) ? g_sk : g_sq)[grow] = sum;
        }
    }
}

// ---------------------------------------------------------------------------
// Fused kernel: attention split-K blocks (first ATT_BLOCKS) + Wo-MLP blocks.
// Attention role: 64 queries (8 warps x 8 q), key chunks of 64, occ 3.
// Wo role: 32 rows, 16-input weight chunks, fits in the 70KB smem footprint.
// ---------------------------------------------------------------------------
#define ATT_SMEM_FLOATS (64*68 * 4 + 64 + 64)

__global__ void __launch_bounds__(256, 3) fused_kernel(
    const float* __restrict__ V, const float* __restrict__ QUERY,
    const float* __restrict__ B1o, const float* __restrict__ B2o,
    const float* __restrict__ B3o)
{
    extern __shared__ float sm[];
    const int t    = threadIdx.x;
    const int lane = t & 31;
    const int w    = t >> 5;

    if (blockIdx.x < ATT_BLOCKS) {
        // ===================== attention role =====================
        float* s_q  = sm;               // [64][68]
        float* s_k  = s_q + 64 * 68;    // [64][68]
        float* s_v  = s_k + 64 * 68;    // [64][68]
        float* s_p  = s_v + 64 * 68;    // [64][68]
        float* s_sk = s_p + 64 * 68;    // [64]
        float* s_sq = s_sk + 64;        // [64]

        const int w8    = w * 8;
        const int bx    = blockIdx.x;
        const int q0    = (bx & 63) * 64;
        const int b     = (bx >> 6) & 3;
        const int split = bx >> 8;       // 0..NSPLIT-1
        const int c0    = (split * (NSEQ / 64)) / NSPLIT;
        const int c1    = ((split + 1) * (NSEQ / 64)) / NSPLIT;

        const float* Qs = g_Qs + (size_t)b * NSEQ * 64;
        const float* Ks = g_Ks + (size_t)b * NSEQ * 64;
        const float* Vb = V    + (size_t)b * NSEQ * 64;

        for (int idx = t; idx < 64 * 16; idx += 256) {
            int r = idx >> 4, c = (idx & 15) * 4;
            *(float4*)(s_q + r * 68 + c) = *(const float4*)(Qs + (size_t)(q0 + r) * 64 + c);
        }
        if (t < 64) s_sq[t] = g_sq[b * NSEQ + q0 + t];

        float m[8], l[8], accx[8], accy[8];
#pragma unroll
        for (int j = 0; j < 8; j++) {
            m[j] = 1e30f; l[j] = 0.f; accx[j] = 0.f; accy[j] = 0.f;
        }

        const int k0 = lane, k1 = lane + 32;

        for (int kc = c0; kc < c1; kc++) {
            __syncthreads();
            const int kb = kc * 64;
            for (int idx = t; idx < 64 * 16; idx += 256) {
                int r = idx >> 4, c = (idx & 15) * 4;
                *(float4*)(s_k + r * 68 + c) = *(const float4*)(Ks + (size_t)(kb + r) * 64 + c);
                *(float4*)(s_v + r * 68 + c) = *(const float4*)(Vb + (size_t)(kb + r) * 64 + c);
            }
            if (t < 64) s_sk[t] = g_sk[b * NSEQ + kb + t];
            __syncthreads();

#pragma unroll
            for (int g = 0; g < 2; g++) {
                float t0x[4], t0y[4], t1x[4], t1y[4];
#pragma unroll
                for (int j = 0; j < 4; j++) { t0x[j] = t0y[j] = t1x[j] = t1y[j] = 0.f; }

#pragma unroll 2
                for (int d = 0; d < 64; d += 4) {
                    float4 a0 = *(const float4*)(s_k + k0 * 68 + d);
                    float4 a1 = *(const float4*)(s_k + k1 * 68 + d);
#pragma unroll
                    for (int j = 0; j < 4; j++) {
                        float4 qv = *(const float4*)(s_q + (w8 + g * 4 + j) * 68 + d);
                        addx2(t0x[j], t0y[j], fminf(a0.x, qv.x), fminf(a0.y, qv.y));
                        addx2(t0x[j], t0y[j], fminf(a0.z, qv.z), fminf(a0.w, qv.w));
                        addx2(t1x[j], t1y[j], fminf(a1.x, qv.x), fminf(a1.y, qv.y));
                        addx2(t1x[j], t1y[j], fminf(a1.z, qv.z), fminf(a1.w, qv.w));
                    }
                }

                const float skk0 = s_sk[k0];
                const float skk1 = s_sk[k1];
                float p0[4], p1[4];
#pragma unroll
                for (int j = 0; j < 4; j++) {
                    const int jq = g * 4 + j;
                    float sqj = s_sq[w8 + jq];
                    float s0 = skk0 + sqj - 2.f * (t0x[j] + t0y[j]);
                    float s1 = skk1 + sqj - 2.f * (t1x[j] + t1y[j]);
                    float c  = fminf(s0, s1);
#pragma unroll
                    for (int off = 16; off >= 1; off >>= 1)
                        c = fminf(c, __shfl_xor_sync(0xffffffffu, c, off));
                    float mn = fminf(m[jq], c);
                    if (mn != m[jq]) {       // warp-uniform branch
                        float alpha = __expf(0.5f * (mn - m[jq]) * (mn + m[jq]));
                        m[jq] = mn;
                        l[jq]    *= alpha;
                        accx[jq] *= alpha;
                        accy[jq] *= alpha;
                    }
                    p0[j] = __expf(0.5f * (mn - s0) * (mn + s0));
                    p1[j] = __expf(0.5f * (mn - s1) * (mn + s1));
                    l[jq] += p0[j] + p1[j];
                }
                *(float4*)(s_p + k0 * 68 + w8 + g * 4) = make_float4(p0[0], p0[1], p0[2], p0[3]);
                *(float4*)(s_p + k1 * 68 + w8 + g * 4) = make_float4(p1[0], p1[1], p1[2], p1[3]);
            }
            __syncwarp();

#pragma unroll 2
            for (int k = 0; k < 64; k++) {
                float4 pA = *(const float4*)(s_p + k * 68 + w8);
                float4 pB = *(const float4*)(s_p + k * 68 + w8 + 4);
                float2 v  = *(const float2*)(s_v + k * 68 + 2 * lane);
                float vdx = dupreg(v.x), vdy = dupreg(v.y);
                fmax2(accx[0], accx[1], pA.x, pA.y, v.x, vdx);
                fmax2(accx[2], accx[3], pA.z, pA.w, v.x, vdx);
                fmax2(accx[4], accx[5], pB.x, pB.y, v.x, vdx);
                fmax2(accx[6], accx[7], pB.z, pB.w, v.x, vdx);
                fmax2(accy[0], accy[1], pA.x, pA.y, v.y, vdy);
                fmax2(accy[2], accy[3], pA.z, pA.w, v.y, vdy);
                fmax2(accy[4], accy[5], pB.x, pB.y, v.y, vdy);
                fmax2(accy[6], accy[7], pB.z, pB.w, v.y, vdy);
            }
        }

        // store partial (m, l, acc) for this split
#pragma unroll
        for (int j = 0; j < 8; j++) {
            float r = l[j];
#pragma unroll
            for (int off = 16; off >= 1; off >>= 1)
                r += __shfl_xor_sync(0xffffffffu, r, off);
            int row = b * NSEQ + q0 + w8 + j;
            size_t poff = (size_t)split * NROWS + row;
            *(float2*)(g_pacc + poff * 64 + 2 * lane) = make_float2(accx[j], accy[j]);
            if (lane == 0) { g_pm[poff] = m[j]; g_pl[poff] = r; }
        }
    } else {
        // ===================== Wo-MLP role (32 rows) =====================
        float* s_x = sm;               // 32*64
        float* s_a = sm + 32 * 64;     // 32*256 h1, then h2 (aliased)
        float* s_w = s_a + 32 * 256;   // up to 64*64

        const int u    = blockIdx.x - ATT_BLOCKS;   // 0..WO_BLOCKS-1
        const int row0 = u * 32;
        const int l4   = lane * 4;
        const int rg4  = w * 4;       // 8 warps x 4 rows

        const float* w1t = g_W1T[1];
        const float* w2t = g_W2T[1];
        const float* w3t = g_W3T[1];

        for (int idx = t; idx < 32 * 16; idx += 256) {
            int r = idx >> 4, c = (idx & 15) * 4;
            *(float4*)(s_x + r * 64 + c) =
                *(const float4*)(QUERY + (size_t)(row0 + r) * 64 + c);
        }

        // Layer 1: 64 -> 256 in 4 chunks of 16 inputs
        {
            float acc[4][8];
#pragma unroll
            for (int r = 0; r < 4; r++)
#pragma unroll
                for (int c = 0; c < 8; c++) acc[r][c] = 0.f;

            for (int ch = 0; ch < 4; ch++) {
                __syncthreads();
                for (int idx = t; idx < 16 * 64; idx += 256) {
                    int i = idx >> 6, o4 = (idx & 63) * 4;
                    *(float4*)(s_w + i * 256 + o4) =
                        *(const float4*)(w1t + (size_t)(ch * 16 + i) * 256 + o4);
                }
                __syncthreads();
#pragma unroll 4
                for (int i = 0; i < 16; i++) {
                    float4 wA = *(const float4*)(s_w + i * 256 + l4);
                    float4 wB = *(const float4*)(s_w + i * 256 + 128 + l4);
#pragma unroll
                    for (int r = 0; r < 4; r++) {
                        float a  = s_x[(rg4 + r) * 64 + ch * 16 + i];
                        float ad = dupreg(a);
                        fmax2(acc[r][0], acc[r][1], a, ad, wA.x, wA.y);
                        fmax2(acc[r][2], acc[r][3], a, ad, wA.z, wA.w);
                        fmax2(acc[r][4], acc[r][5], a, ad, wB.x, wB.y);
                        fmax2(acc[r][6], acc[r][7], a, ad, wB.z, wB.w);
                    }
                }
            }
            float4 bA = *(const float4*)(B1o + l4);
            float4 bB = *(const float4*)(B1o + 128 + l4);
#pragma unroll
            for (int r = 0; r < 4; r++) {
                int row = rg4 + r;
                *(float4*)(s_a + row * 256 + l4) = make_float4(
                    fmaxf(acc[r][0] + bA.x, 0.f), fmaxf(acc[r][1] + bA.y, 0.f),
                    fmaxf(acc[r][2] + bA.z, 0.f), fmaxf(acc[r][3] + bA.w, 0.f));
                *(float4*)(s_a + row * 256 + 128 + l4) = make_float4(
                    fmaxf(acc[r][4] + bB.x, 0.f), fmaxf(acc[r][5] + bB.y, 0.f),
                    fmaxf(acc[r][6] + bB.z, 0.f), fmaxf(acc[r][7] + bB.w, 0.f));
            }
        }

        // Layer 2: 256 -> 256 in 16 chunks of 16 inputs (h2 aliased into s_a)
        {
            float acc[4][8];
#pragma unroll
            for (int r = 0; r < 4; r++)
#pragma unroll
                for (int c = 0; c < 8; c++) acc[r][c] = 0.f;

            for (int ch = 0; ch < 16; ch++) {
                __syncthreads();
                for (int idx = t; idx < 16 * 64; idx += 256) {
                    int i = idx >> 6, o4 = (idx & 63) * 4;
                    *(float4*)(s_w + i * 256 + o4) =
                        *(const float4*)(w2t + (size_t)(ch * 16 + i) * 256 + o4);
                }
                __syncthreads();
#pragma unroll 4
                for (int i = 0; i < 16; i++) {
                    float4 wA = *(const float4*)(s_w + i * 256 + l4);
                    float4 wB = *(const float4*)(s_w + i * 256 + 128 + l4);
#pragma unroll
                    for (int r = 0; r < 4; r++) {
                        float a  = s_a[(rg4 + r) * 256 + ch * 16 + i];
                        float ad = dupreg(a);
                        fmax2(acc[r][0], acc[r][1], a, ad, wA.x, wA.y);
                        fmax2(acc[r][2], acc[r][3], a, ad, wA.z, wA.w);
                        fmax2(acc[r][4], acc[r][5], a, ad, wB.x, wB.y);
                        fmax2(acc[r][6], acc[r][7], a, ad, wB.z, wB.w);
                    }
                }
            }
            __syncthreads();   // all h1 reads complete before overwrite
            float4 bA = *(const float4*)(B2o + l4);
            float4 bB = *(const float4*)(B2o + 128 + l4);
#pragma unroll
            for (int r = 0; r < 4; r++) {
                int row = rg4 + r;
                *(float4*)(s_a + row * 256 + l4) = make_float4(
                    fmaxf(acc[r][0] + bA.x, 0.f), fmaxf(acc[r][1] + bA.y, 0.f),
                    fmaxf(acc[r][2] + bA.z, 0.f), fmaxf(acc[r][3] + bA.w, 0.f));
                *(float4*)(s_a + row * 256 + 128 + l4) = make_float4(
                    fmaxf(acc[r][4] + bB.x, 0.f), fmaxf(acc[r][5] + bB.y, 0.f),
                    fmaxf(acc[r][6] + bB.z, 0.f), fmaxf(acc[r][7] + bB.w, 0.f));
            }
        }

        // Layer 3: 256 -> 64 in 4 chunks of 64 inputs -> g_Wo
        {
            const int l2 = lane * 2;
            float ax[4], ay[4];
#pragma unroll
            for (int r = 0; r < 4; r++) { ax[r] = 0.f; ay[r] = 0.f; }

            for (int ch = 0; ch < 4; ch++) {
                __syncthreads();
                for (int idx = t; idx < 64 * 16; idx += 256) {
                    int i = idx >> 4, o4 = (idx & 15) * 4;
                    *(float4*)(s_w + i * 64 + o4) =
                        *(const float4*)(w3t + (size_t)(ch * 64 + i) * 64 + o4);
                }
                __syncthreads();
#pragma unroll 4
                for (int i = 0; i < 64; i++) {
                    float2 wv = *(const float2*)(s_w + i * 64 + l2);
#pragma unroll
                    for (int r = 0; r < 4; r++) {
                        float a  = s_a[(rg4 + r) * 256 + ch * 64 + i];
                        float ad = dupreg(a);
                        fmax2(ax[r], ay[r], a, ad, wv.x, wv.y);
                    }
                }
            }

            float2 bv = *(const float2*)(B3o + l2);
#pragma unroll
            for (int r = 0; r < 4; r++) {
                size_t grow = (size_t)(row0 + rg4 + r);
                *(float2*)(g_Wo + grow * 64 + l2) =
                    make_float2(ax[r] + bv.x, ay[r] + bv.y);
            }
        }
    }
}

// ---------------------------------------------------------------------------
// Merge: combine split partials exactly, apply Wo. 1 warp per q-row.
// ---------------------------------------------------------------------------
__global__ void __launch_bounds__(256, 8) merge_kernel(float* __restrict__ out)
{
    const int t    = threadIdx.x;
    const int row  = blockIdx.x * 8 + (t >> 5);
    const int lane = t & 31;

    float mv[NSPLIT], lv[NSPLIT];
    float mm = 1e30f;
#pragma unroll
    for (int s = 0; s < NSPLIT; s++) {
        mv[s] = g_pm[(size_t)s * NROWS + row];
        lv[s] = g_pl[(size_t)s * NROWS + row];
        mm = fminf(mm, mv[s]);
    }
    float wgt[NSPLIT];
    float lsum = 0.f;
#pragma unroll
    for (int s = 0; s < NSPLIT; s++) {
        wgt[s] = __expf(0.5f * (mm - mv[s]) * (mm + mv[s]));
        lsum += wgt[s] * lv[s];
    }
    float inv = 1.0f / lsum;

    size_t o = (size_t)row * 64 + 2 * lane;
    float ax = 0.f, ay = 0.f;
#pragma unroll
    for (int s = 0; s < NSPLIT; s++) {
        float2 a = *(const float2*)(g_pacc + ((size_t)s * NROWS + row) * 64 + 2 * lane);
        ax += wgt[s] * a.x;
        ay += wgt[s] * a.y;
    }
    float2 wv = *(const float2*)(g_Wo + o);
    float2 r;
    r.x = ax * inv * wv.x;
    r.y = ay * inv * wv.y;
    *(float2*)(out + o) = r;
}

// ---------------------------------------------------------------------------
extern "C" void kernel_launch(void* const* d_in, const int* in_sizes, int n_in,
                              void* d_out, int out_size)
{
    (void)in_sizes; (void)n_in; (void)out_size;
    const float* KEY   = (const float*)d_in[0];
    const float* VALUE = (const float*)d_in[1];
    const float* QUERY = (const float*)d_in[2];
    const float* W1w = (const float*)d_in[3],  *W1b = (const float*)d_in[4];
    const float* W2w = (const float*)d_in[5],  *W2b = (const float*)d_in[6];
    const float* W3w = (const float*)d_in[7],  *W3b = (const float*)d_in[8];
    const float* O1w = (const float*)d_in[9],  *O1b = (const float*)d_in[10];
    const float* O2w = (const float*)d_in[11], *O2b = (const float*)d_in[12];
    const float* O3w = (const float*)d_in[13], *O3b = (const float*)d_in[14];

    cudaFuncSetAttribute(mlp_kernel, cudaFuncAttributeMaxDynamicSharedMemorySize,
                         MLP_SMEM_FLOATS * sizeof(float));
    cudaFuncSetAttribute(fused_kernel, cudaFuncAttributeMaxDynamicSharedMemorySize,
                         ATT_SMEM_FLOATS * sizeof(float));

    transpose_w_kernel<<<256, 256>>>(W1w, W2w, W3w, O1w, O2w, O3w);

    dim3 mlp_grid(NROWS / 64, 2);   // modes 0 (KEY) and 1 (QUERY) only
    mlp_kernel<<<mlp_grid, 256, MLP_SMEM_FLOATS * sizeof(float)>>>(
        KEY, QUERY, W1b, W2b, W3b);

    fused_kernel<<<ATT_BLOCKS + WO_BLOCKS, 256, ATT_SMEM_FLOATS * sizeof(float)>>>(
        VALUE, QUERY, O1b, O2b, O3b);

    merge_kernel<<<NROWS / 8, 256>>>((float*)d_out);
}